// round 12
// baseline (speedup 1.0000x reference)
#include <cuda_runtime.h>
#include <cstdint>

#define B4   4      // 2*BS concatenated batch
#define Dd   256    // feature dim
#define D2   512
#define NN   1024   // keypoints
#define LL   6

// Scratch (device globals; no allocation allowed)
__device__ float g_Q[B4 * Dd * NN];
__device__ float g_K[B4 * Dd * NN];
__device__ float g_V[B4 * Dd * NN];
__device__ float g_Xatt[B4 * Dd * NN];
__device__ float g_Y1[B4 * D2 * NN];
__device__ float g_bnsum[D2];
__device__ float g_bnsq[D2];
__device__ float g_W1c[LL * D2 * D2];   // composite [W1a | W1b@Wm] per layer
__device__ float g_b1c[LL * D2];        // composite b1 + W1b@bm

__device__ __forceinline__ uint32_t f2tf(float f) {
    uint32_t u; asm("cvt.rna.tf32.f32 %0, %1;" : "=r"(u) : "f"(f)); return u;
}
__device__ __forceinline__ void mma8(float c[4], const uint32_t a[4], const uint32_t b[2]) {
    asm volatile("mma.sync.aligned.m16n8k8.row.col.f32.tf32.tf32.f32 "
        "{%0,%1,%2,%3}, {%4,%5,%6,%7}, {%8,%9}, {%0,%1,%2,%3};"
        : "+f"(c[0]), "+f"(c[1]), "+f"(c[2]), "+f"(c[3])
        : "r"(a[0]), "r"(a[1]), "r"(a[2]), "r"(a[3]), "r"(b[0]), "r"(b[1]));
}
__device__ __forceinline__ void cp16(void* dst, const void* src) {
    uint32_t d = (uint32_t)__cvta_generic_to_shared(dst);
    asm volatile("cp.async.ca.shared.global [%0], [%1], 16;" :: "r"(d), "l"(src));
}

// ---------------------------------------------------------------------------
// cp.async 3-stage pipelined tf32 GEMM core, BK=32, register-level fragment
// double buffering. Block 64(M) x 128(N), 256 threads (8 warps, 32x32 warp
// tile). A smem [m][k] stride 36, B smem [k][n] stride 136 (conflict-free).
// ---------------------------------------------------------------------------
template<int CONCAT>
__device__ __forceinline__ void gemm_core_cpa32(
    const float* __restrict__ Wp, int I,
    const float* __restrict__ XA, const float* __restrict__ XB,
    int col0, uint32_t (*As)[64][36], uint32_t (*Bs)[32][136],
    float acc[2][4][4])
{
    int t = threadIdx.x;
    int lane = t & 31, w = t >> 5;
    int g = lane >> 2, q = lane & 3;
    int warp_m = (w >> 2) * 32, warp_n = (w & 3) * 32;
    int ar = t >> 2, ak = (t & 3) * 8;   // A: 2x16B per thread
    int bk = t >> 4, bn = (t & 15) * 8;  // B: 4x16B per thread (k and k+16)

    auto issue = [&](int kt) {
        int buf = kt % 3;
        int k0 = kt << 5;
        const float* wr = &Wp[(size_t)ar * I + k0 + ak];
        cp16(&As[buf][ar][ak],     wr);
        cp16(&As[buf][ar][ak + 4], wr + 4);
        #pragma unroll
        for (int half = 0; half < 2; half++) {
            int ch = k0 + bk + half * 16;
            const float* src = XA; int chl = ch;
            if (CONCAT && ch >= 256) { src = XB; chl = ch - 256; }
            const float* gp = &src[(size_t)chl * NN + col0 + bn];
            cp16(&Bs[buf][bk + half * 16][bn],     gp);
            cp16(&Bs[buf][bk + half * 16][bn + 4], gp + 4);
        }
        asm volatile("cp.async.commit_group;" ::: "memory");
    };

    int nk = I >> 5;
    issue(0);
    if (nk > 1) issue(1);

    uint32_t aF[2][8], bF[2][8];

    for (int kt = 0; kt < nk; kt++) {
        if (kt + 1 < nk) asm volatile("cp.async.wait_group 1;" ::: "memory");
        else             asm volatile("cp.async.wait_group 0;" ::: "memory");
        __syncthreads();
        int cur = kt % 3;

        auto ldfrag = [&](int ks, int pb) {
            #pragma unroll
            for (int nt = 0; nt < 4; nt++) {
                int n = warp_n + nt * 8 + g;
                bF[pb][nt * 2 + 0] = Bs[cur][ks + q][n];
                bF[pb][nt * 2 + 1] = Bs[cur][ks + q + 4][n];
            }
            #pragma unroll
            for (int mt = 0; mt < 2; mt++) {
                int m = warp_m + mt * 16 + g;
                aF[pb][mt * 4 + 0] = As[cur][m][ks + q];
                aF[pb][mt * 4 + 1] = As[cur][m + 8][ks + q];
                aF[pb][mt * 4 + 2] = As[cur][m][ks + q + 4];
                aF[pb][mt * 4 + 3] = As[cur][m + 8][ks + q + 4];
            }
        };

        ldfrag(0, 0);
        #pragma unroll
        for (int s = 0; s < 4; s++) {
            if (s < 3) ldfrag((s + 1) * 8, (s + 1) & 1);
            int pb = s & 1;
            #pragma unroll
            for (int mt = 0; mt < 2; mt++)
                #pragma unroll
                for (int nt = 0; nt < 4; nt++)
                    mma8(acc[mt][nt], &aF[pb][mt * 4], &bF[pb][nt * 2]);
        }
        if (kt + 2 < nk) issue(kt + 2);
    }
}

// Register-staged double-buffered BK=16 core with BN+ReLU transform on the
// B-load path; scale/shift come from a block-local smem table.
__device__ __forceinline__ void gemm_core_bnrelu(
    const float* __restrict__ Wp, int I,
    const float* __restrict__ XA,
    int col0, uint32_t (*As)[64][20], uint32_t (*Bs)[16][136],
    const float* __restrict__ sSc, const float* __restrict__ sSh,
    float acc[2][4][4])
{
    int t = threadIdx.x;
    int lane = t & 31, w = t >> 5;
    int g = lane >> 2, q = lane & 3;
    int warp_m = (w >> 2) * 32, warp_n = (w & 3) * 32;
    int ar = t >> 2, ak = (t & 3) * 4;
    int bk = t >> 4, bn = (t & 15) * 8;

    float4 aReg;
    float4 bReg[2];
    float bSc = 0.f, bSh = 0.f;

    auto load_tile = [&](int k0) {
        aReg = *(const float4*)&Wp[(size_t)ar * I + k0 + ak];
        int ch = k0 + bk;
        const float* gp = &XA[(size_t)ch * NN + col0 + bn];
        bSc = sSc[ch]; bSh = sSh[ch];
        bReg[0] = *(const float4*)gp;
        bReg[1] = *(const float4*)(gp + 4);
    };
    auto store_tile = [&](int buf) {
        uint4 s;
        s.x = f2tf(aReg.x); s.y = f2tf(aReg.y);
        s.z = f2tf(aReg.z); s.w = f2tf(aReg.w);
        *(uint4*)&As[buf][ar][ak] = s;
        #pragma unroll
        for (int u = 0; u < 2; u++) {
            float4 xv = bReg[u];
            xv.x = fmaxf(fmaf(xv.x, bSc, bSh), 0.f);
            xv.y = fmaxf(fmaf(xv.y, bSc, bSh), 0.f);
            xv.z = fmaxf(fmaf(xv.z, bSc, bSh), 0.f);
            xv.w = fmaxf(fmaf(xv.w, bSc, bSh), 0.f);
            uint4 o;
            o.x = f2tf(xv.x); o.y = f2tf(xv.y);
            o.z = f2tf(xv.z); o.w = f2tf(xv.w);
            *(uint4*)&Bs[buf][bk][bn + u * 4] = o;
        }
    };

    int nk = I >> 4;
    load_tile(0);
    store_tile(0);
    __syncthreads();

    uint32_t aF[2][8], bF[2][8];

    for (int kt = 0; kt < nk; kt++) {
        int cur = kt & 1;
        if (kt + 1 < nk) load_tile((kt + 1) << 4);

        auto ldfrag = [&](int ks, int pb) {
            #pragma unroll
            for (int nt = 0; nt < 4; nt++) {
                int n = warp_n + nt * 8 + g;
                bF[pb][nt * 2 + 0] = Bs[cur][ks + q][n];
                bF[pb][nt * 2 + 1] = Bs[cur][ks + q + 4][n];
            }
            #pragma unroll
            for (int mt = 0; mt < 2; mt++) {
                int m = warp_m + mt * 16 + g;
                aF[pb][mt * 4 + 0] = As[cur][m][ks + q];
                aF[pb][mt * 4 + 1] = As[cur][m + 8][ks + q];
                aF[pb][mt * 4 + 2] = As[cur][m][ks + q + 4];
                aF[pb][mt * 4 + 3] = As[cur][m + 8][ks + q + 4];
            }
        };
        ldfrag(0, 0);
        #pragma unroll
        for (int s = 0; s < 2; s++) {
            if (s < 1) ldfrag(8, 1);
            int pb = s & 1;
            #pragma unroll
            for (int mt = 0; mt < 2; mt++)
                #pragma unroll
                for (int nt = 0; nt < 4; nt++)
                    mma8(acc[mt][nt], &aF[pb][mt * 4], &bF[pb][nt * 2]);
        }
        if (kt + 1 < nk) store_tile(cur ^ 1);
        __syncthreads();
    }
}

// Epilogue; STATS=1 additionally accumulates per-channel sum/sumsq into
// g_bnsum/g_bnsq (quad shfl-reduce, then atomicAdd from lane q==0).
template<int STATS>
__device__ __forceinline__ void gemm_epilogue(
    float acc[2][4][4], const float* __restrict__ bias,
    float* __restrict__ Ob, int row0, int col0, int addOut)
{
    int t = threadIdx.x; int lane = t & 31; int w = t >> 5;
    int g = lane >> 2, q = lane & 3;
    int warp_m = (w >> 2) * 32, warp_n = (w & 3) * 32;
    #pragma unroll
    for (int mt = 0; mt < 2; mt++) {
        #pragma unroll
        for (int half = 0; half < 2; half++) {
            int r = row0 + warp_m + mt * 16 + g + half * 8;
            float bb = bias[r];
            float rs = 0.f, rq = 0.f;
            #pragma unroll
            for (int nt = 0; nt < 4; nt++) {
                int c = col0 + warp_n + nt * 8 + 2 * q;
                float* p = &Ob[(size_t)r * NN + c];
                float v0 = acc[mt][nt][half * 2 + 0] + bb;
                float v1 = acc[mt][nt][half * 2 + 1] + bb;
                if (addOut) { float2 e = *(const float2*)p; v0 += e.x; v1 += e.y; }
                float2 o; o.x = v0; o.y = v1;
                *(float2*)p = o;
                if (STATS) { rs += v0 + v1; rq += v0 * v0 + v1 * v1; }
            }
            if (STATS) {
                rs += __shfl_xor_sync(0xffffffffu, rs, 1);
                rs += __shfl_xor_sync(0xffffffffu, rs, 2);
                rq += __shfl_xor_sync(0xffffffffu, rq, 1);
                rq += __shfl_xor_sync(0xffffffffu, rq, 2);
                if (q == 0) {
                    atomicAdd(&g_bnsum[r], rs);
                    atomicAdd(&g_bnsq[r], rq);
                }
            }
        }
    }
}

// Fused Q/K/V projection: logical rows 0-255 = Q, 256-511 = K, 512-767 = V.
// Block (0,0,0) also re-zeroes the BN accumulators for this layer's conv1.
__global__ __launch_bounds__(256, 2) void qkv_mma(
    const float* __restrict__ Wq, const float* __restrict__ bq,
    const float* __restrict__ Wk, const float* __restrict__ bk,
    const float* __restrict__ Wv, const float* __restrict__ bv,
    const float* __restrict__ X, int xorMask,
    float* __restrict__ Qo, float* __restrict__ Ko, float* __restrict__ Vo)
{
    extern __shared__ uint32_t sm[];
    uint32_t (*As)[64][36]  = (uint32_t(*)[64][36])sm;
    uint32_t (*Bs)[32][136] = (uint32_t(*)[32][136])(sm + 3 * 64 * 36);
    int b    = blockIdx.z;
    int row0 = blockIdx.y * 64;
    int col0 = blockIdx.x * 128;
    if (blockIdx.x == 0 && blockIdx.y == 0 && blockIdx.z == 0) {
        int t = threadIdx.x;
        g_bnsum[t] = 0.f; g_bnsum[t + 256] = 0.f;
        g_bnsq[t]  = 0.f; g_bnsq[t + 256]  = 0.f;
    }
    int sel  = row0 >> 8;
    int lrow0 = row0 & 255;
    const float* W; const float* bias; float* Out; int xb;
    if (sel == 0)      { W = Wq; bias = bq; Out = Qo; xb = b; }
    else if (sel == 1) { W = Wk; bias = bk; Out = Ko; xb = b ^ xorMask; }
    else               { W = Wv; bias = bv; Out = Vo; xb = b ^ xorMask; }
    const float* XA = X + (size_t)xb * Dd * NN;
    float acc[2][4][4] = {};
    gemm_core_cpa32<0>(W + (size_t)lrow0 * Dd, Dd, XA, nullptr, col0, As, Bs, acc);
    gemm_epilogue<0>(acc, bias, Out + (size_t)b * Dd * NN, lrow0, col0, 0);
}

// conv1 on [X ; X2] with composite weights; accumulates BN stats.
__global__ __launch_bounds__(256, 2) void conv1_mma(
    const float* __restrict__ W, const float* __restrict__ bias,
    const float* __restrict__ X, const float* __restrict__ X2,
    float* __restrict__ Out)
{
    extern __shared__ uint32_t sm[];
    uint32_t (*As)[64][36]  = (uint32_t(*)[64][36])sm;
    uint32_t (*Bs)[32][136] = (uint32_t(*)[32][136])(sm + 3 * 64 * 36);
    int b    = blockIdx.z;
    int row0 = blockIdx.y * 64;
    int col0 = blockIdx.x * 128;
    const float* XA = X + (size_t)b * 256 * NN;
    const float* XB = X2 + (size_t)b * 256 * NN;
    float acc[2][4][4] = {};
    gemm_core_cpa32<1>(W + (size_t)row0 * D2, D2, XA, XB, col0, As, Bs, acc);
    gemm_epilogue<1>(acc, bias, Out + (size_t)b * D2 * NN, row0, col0, 0);
}

// conv2: recomputes BN scale/shift per block from accumulators, then GEMM
// with fused BN+ReLU on the B path (+residual into Dsc).
__global__ __launch_bounds__(256, 2) void conv_bnrelu(
    const float* __restrict__ W, const float* __restrict__ bias,
    const float* __restrict__ gvec, const float* __restrict__ betav,
    const float* __restrict__ X, float* __restrict__ Out)
{
    __shared__ uint32_t As[2][64][20];
    __shared__ uint32_t Bs[2][16][136];
    __shared__ float sSc[D2], sSh[D2];
    int t = threadIdx.x;
    #pragma unroll
    for (int u = 0; u < 2; u++) {
        int c = t + u * 256;
        float s = g_bnsum[c], sq = g_bnsq[c];
        float mean = s * (1.0f / 4096.0f);
        float var  = sq * (1.0f / 4096.0f) - mean * mean;
        float rstd = rsqrtf(var + 1e-5f);
        float sc = gvec[c] * rstd;
        sSc[c] = sc;
        sSh[c] = betav[c] - mean * sc;
    }
    __syncthreads();
    int b    = blockIdx.z;
    int row0 = blockIdx.y * 64;
    int col0 = blockIdx.x * 128;
    const float* XA = X + (size_t)b * (size_t)D2 * NN;
    float acc[2][4][4] = {};
    gemm_core_bnrelu(W + (size_t)row0 * D2, D2, XA, col0, As, Bs, sSc, sSh, acc);
    gemm_epilogue<0>(acc, bias, Out + (size_t)b * Dd * NN, row0, col0, 1);
}

// ---------------------------------------------------------------------------
// Composite-weight precompute (once per launch).
// ---------------------------------------------------------------------------
__global__ __launch_bounds__(256) void copy_w1a(const float* __restrict__ W1)
{
    size_t i = (size_t)blockIdx.x * 256 + threadIdx.x;   // float4 index
    int l   = (int)(i / (D2 * 64));
    int rem = (int)(i % (D2 * 64));
    int r = rem >> 6, c4 = (rem & 63) * 4;
    *(float4*)&g_W1c[(size_t)l * D2 * D2 + (size_t)r * D2 + c4] =
        *(const float4*)&W1[(size_t)l * D2 * D2 + (size_t)r * D2 + c4];
}

__global__ __launch_bounds__(256) void compose_w1(
    const float* __restrict__ W1, const float* __restrict__ Wm)
{
    __shared__ float Asm[64][17];   // [row][k]
    __shared__ float Bsm[16][68];   // [k][col]
    int l = blockIdx.z;
    int row0 = blockIdx.y * 64;
    int col0 = blockIdx.x * 64;
    const float* W1l = W1 + (size_t)l * D2 * D2;
    const float* Wml = Wm + (size_t)l * Dd * Dd;
    float* Out = g_W1c + (size_t)l * D2 * D2;
    int t = threadIdx.x; int tx = t & 15, ty = t >> 4;
    float acc[4][4] = {};
    for (int k0 = 0; k0 < 256; k0 += 16) {
        int lr = t >> 2, lk = (t & 3) * 4;
        float4 wv = *(const float4*)&W1l[(size_t)(row0 + lr) * D2 + 256 + k0 + lk];
        Asm[lr][lk + 0] = wv.x; Asm[lr][lk + 1] = wv.y;
        Asm[lr][lk + 2] = wv.z; Asm[lr][lk + 3] = wv.w;
        float4 xv = *(const float4*)&Wml[(size_t)(k0 + (t >> 4)) * Dd + col0 + (t & 15) * 4];
        *(float4*)&Bsm[t >> 4][(t & 15) * 4] = xv;
        __syncthreads();
        #pragma unroll
        for (int k = 0; k < 16; k++) {
            float a0 = Asm[ty * 4 + 0][k], a1 = Asm[ty * 4 + 1][k];
            float a2 = Asm[ty * 4 + 2][k], a3 = Asm[ty * 4 + 3][k];
            float4 bv = *(const float4*)&Bsm[k][tx * 4];
            acc[0][0] += a0 * bv.x; acc[0][1] += a0 * bv.y; acc[0][2] += a0 * bv.z; acc[0][3] += a0 * bv.w;
            acc[1][0] += a1 * bv.x; acc[1][1] += a1 * bv.y; acc[1][2] += a1 * bv.z; acc[1][3] += a1 * bv.w;
            acc[2][0] += a2 * bv.x; acc[2][1] += a2 * bv.y; acc[2][2] += a2 * bv.z; acc[2][3] += a2 * bv.w;
            acc[3][0] += a3 * bv.x; acc[3][1] += a3 * bv.y; acc[3][2] += a3 * bv.z; acc[3][3] += a3 * bv.w;
        }
        __syncthreads();
    }
    #pragma unroll
    for (int i = 0; i < 4; i++)
        #pragma unroll
        for (int j = 0; j < 4; j++)
            Out[(size_t)(row0 + ty * 4 + i) * D2 + 256 + col0 + tx * 4 + j] = acc[i][j];
}

__global__ __launch_bounds__(256) void compose_b1(
    const float* __restrict__ W1, const float* __restrict__ bm,
    const float* __restrict__ b1)
{
    int i = blockIdx.x * 256 + threadIdx.x;   // LL*D2
    int l = i >> 9, o = i & 511;
    const float* wrow = W1 + (size_t)l * D2 * D2 + (size_t)o * D2 + 256;
    const float* bml = bm + (size_t)l * Dd;
    float s = b1[(size_t)l * D2 + o];
    for (int c = 0; c < 256; c++) s += wrow[c] * bml[c];
    g_b1c[i] = s;
}

// ---------------------------------------------------------------------------
// Flash attention, tf32 mma, cp.async double-buffered K/V, transposed PV.
// Br=128 q-rows per block (256 threads, 8 warps; warp w owns rows
// [16w,16w+16)) x Bc=64 kv-cols per iter -> K/V loads amortized over 2x the
// q-rows vs the 64-row version. Q pre-scaled by 1/8 at smem store (exact).
// Smem: Qs[128][68] tf32, Ks 2x[64][72], Vs 2x[64][68], Ps[64][136] (P^T,
// aliased as Osf[64][136] fp32 for the output staging).
// ---------------------------------------------------------------------------
__global__ __launch_bounds__(256) void attn_mma(
    const float* __restrict__ Q, const float* __restrict__ K,
    const float* __restrict__ V,
    const float* __restrict__ M0, const float* __restrict__ M1,
    float* __restrict__ Xatt)
{
    extern __shared__ uint32_t smu[];
    uint32_t (*Qs)[68]     = (uint32_t(*)[68])smu;                                 // [n][d] 128x68
    uint32_t (*Ks)[64][72] = (uint32_t(*)[64][72])(smu + 128 * 68);                // 2x [d][m]
    uint32_t (*Vs)[64][68] = (uint32_t(*)[64][68])(smu + 128 * 68 + 2 * 64 * 72);  // 2x [d][m]
    uint32_t (*Ps)[136]    = (uint32_t(*)[136])(smu + 128 * 68 + 2 * 64 * 72 + 2 * 64 * 68); // [m][n]
    float    (*Osf)[136]   = (float(*)[136])Ps;

    int bh = blockIdx.y; int b = bh >> 2, h = bh & 3;
    int n0 = blockIdx.x * 128;
    int t = threadIdx.x;
    int lane = t & 31, w = t >> 5;
    int g = lane >> 2, q = lane & 3;
    int rowb = w * 16;

    const float* Qb = Q + (size_t)b * Dd * NN;
    const float* Kb = K + (size_t)b * Dd * NN;
    const float* Vb = V + (size_t)b * Dd * NN;
    const float* Mb = (b < 2) ? M0 + (size_t)b * NN * NN
                              : M1 + (size_t)(b - 2) * NN * NN;

    // Q tile transpose-load -> Qs[n][d], pre-scaled by 1/8 (exact)
    {
        int d = t >> 2, nc = (t & 3) * 32;
        const float* gp = &Qb[(size_t)(d * 4 + h) * NN + n0 + nc];
        #pragma unroll
        for (int u = 0; u < 8; u++) {
            float4 v = *(const float4*)(gp + u * 4);
            Qs[nc + u * 4 + 0][d] = __float_as_uint(v.x * 0.125f);
            Qs[nc + u * 4 + 1][d] = __float_as_uint(v.y * 0.125f);
            Qs[nc + u * 4 + 2][d] = __float_as_uint(v.z * 0.125f);
            Qs[nc + u * 4 + 3][d] = __float_as_uint(v.w * 0.125f);
        }
    }

    auto issue_kv = [&](int it) {
        int buf = it & 1, mt = it << 6;
        int cr = t >> 2;            // row 0..63
        int cc = (t & 3) * 16;      // col base 0/16/32/48
        const float* gk = &Kb[(size_t)(cr * 4 + h) * NN + mt + cc];
        const float* gv = &Vb[(size_t)(cr * 4 + h) * NN + mt + cc];
        #pragma unroll
        for (int u = 0; u < 4; u++) {
            cp16(&Ks[buf][cr][cc + u * 4], gk + u * 4);
            cp16(&Vs[buf][cr][cc + u * 4], gv + u * 4);
        }
        asm volatile("cp.async.commit_group;" ::: "memory");
    };

    float oacc[4][2][4] = {};   // [df][nf][c]: rows d=df*16+g(+8), cols n=rowb+{2q,2q+1}(+8)
    float m0r = -1e30f, m1r = -1e30f, l0 = 0.f, l1 = 0.f;
    int r0g = n0 + rowb + g, r1g = r0g + 8;

    issue_kv(0);

    for (int it = 0; it < 16; it++) {
        int buf = it & 1, mt = it << 6;
        asm volatile("cp.async.wait_group 0;" ::: "memory");
        __syncthreads();
        if (it + 1 < 16) issue_kv(it + 1);

        // ---- S = Q^T K : rows rowb..rowb+15, cols m 0..63 ----
        float sacc[8][4] = {};
        #pragma unroll
        for (int ks = 0; ks < 8; ks++) {
            int kk = ks * 8;
            uint32_t a[4];
            a[0] = Qs[rowb + g][kk + q];
            a[1] = Qs[rowb + g + 8][kk + q];
            a[2] = Qs[rowb + g][kk + q + 4];
            a[3] = Qs[rowb + g + 8][kk + q + 4];
            #pragma unroll
            for (int nf = 0; nf < 8; nf++) {
                uint32_t bb[2];
                bb[0] = Ks[buf][kk + q][nf * 8 + g];
                bb[1] = Ks[buf][kk + q + 4][nf * 8 + g];
                mma8(sacc[nf], a, bb);
            }
        }

        // ---- mask + online softmax (scale already folded into Q) ----
        const float* mr0 = Mb + (size_t)r0g * NN + mt;
        const float* mr1 = Mb + (size_t)r1g * NN + mt;
        float v0[16], v1[16];
        float rm0 = -1e30f, rm1 = -1e30f;
        #pragma unroll
        for (int nf = 0; nf < 8; nf++) {
            int c = nf * 8 + 2 * q;
            float2 k0v = *(const float2*)&mr0[c];
            float2 k1v = *(const float2*)&mr1[c];
            v0[2 * nf]     = sacc[nf][0] * k0v.x;
            v0[2 * nf + 1] = sacc[nf][1] * k0v.y;
            v1[2 * nf]     = sacc[nf][2] * k1v.x;
            v1[2 * nf + 1] = sacc[nf][3] * k1v.y;
            rm0 = fmaxf(rm0, fmaxf(v0[2 * nf], v0[2 * nf + 1]));
            rm1 = fmaxf(rm1, fmaxf(v1[2 * nf], v1[2 * nf + 1]));
        }
        rm0 = fmaxf(rm0, __shfl_xor_sync(0xffffffffu, rm0, 1));
        rm0 = fmaxf(rm0, __shfl_xor_sync(0xffffffffu, rm0, 2));
        rm1 = fmaxf(rm1, __shfl_xor_sync(0xffffffffu, rm1, 1));
        rm1 = fmaxf(rm1, __shfl_xor_sync(0xffffffffu, rm1, 2));
        float nm0 = fmaxf(m0r, rm0), nm1 = fmaxf(m1r, rm1);
        float rs0 = 0.f, rs1 = 0.f;
        #pragma unroll
        for (int i = 0; i < 16; i++) {
            v0[i] = __expf(v0[i] - nm0); rs0 += v0[i];
            v1[i] = __expf(v1[i] - nm1); rs1 += v1[i];
        }
        rs0 += __shfl_xor_sync(0xffffffffu, rs0, 1);
        rs0 += __shfl_xor_sync(0xffffffffu, rs0, 2);
        rs1 += __shfl_xor_sync(0xffffffffu, rs1, 1);
        rs1 += __shfl_xor_sync(0xffffffffu, rs1, 2);
        float f0 = __expf(m0r - nm0), f1 = __expf(m1r - nm1);
        m0r = nm0; m1r = nm1;
        l0 = l0 * f0 + rs0;
        l1 = l1 * f1 + rs1;

        // rescale accumulators: per-column factors fetched from owning lanes
        {
            float fA = __shfl_sync(0xffffffffu, f0, 8 * q);
            float fB = __shfl_sync(0xffffffffu, f0, 8 * q + 4);
            float fC = __shfl_sync(0xffffffffu, f1, 8 * q);
            float fD = __shfl_sync(0xffffffffu, f1, 8 * q + 4);
            #pragma unroll
            for (int df = 0; df < 4; df++) {
                oacc[df][0][0] *= fA; oacc[df][0][1] *= fB;
                oacc[df][0][2] *= fA; oacc[df][0][3] *= fB;
                oacc[df][1][0] *= fC; oacc[df][1][1] *= fD;
                oacc[df][1][2] *= fC; oacc[df][1][3] *= fD;
            }
        }

        // store P transposed: Ps[m][n] (intra-warp: own 16 n-columns only)
        #pragma unroll
        for (int nf = 0; nf < 8; nf++) {
            Ps[nf * 8 + 2 * q][rowb + g]         = __float_as_uint(v0[2 * nf]);
            Ps[nf * 8 + 2 * q + 1][rowb + g]     = __float_as_uint(v0[2 * nf + 1]);
            Ps[nf * 8 + 2 * q][rowb + g + 8]     = __float_as_uint(v1[2 * nf]);
            Ps[nf * 8 + 2 * q + 1][rowb + g + 8] = __float_as_uint(v1[2 * nf + 1]);
        }
        __syncwarp();

        // ---- O^T += V P^T ----
        #pragma unroll
        for (int ks = 0; ks < 8; ks++) {
            int kk = ks * 8;
            uint32_t bb0[2], bb1[2];
            bb0[0] = Ps[kk + q][rowb + g];
            bb0[1] = Ps[kk + q + 4][rowb + g];
            bb1[0] = Ps[kk + q][rowb + 8 + g];
            bb1[1] = Ps[kk + q + 4][rowb + 8 + g];
            #pragma unroll
            for (int df = 0; df < 4; df++) {
                uint32_t a[4];
                a[0] = Vs[buf][df * 16 + g][kk + q];
                a[1] = Vs[buf][df * 16 + 8 + g][kk + q];
                a[2] = Vs[buf][df * 16 + g][kk + q + 4];
                a[3] = Vs[buf][df * 16 + 8 + g][kk + q + 4];
                mma8(oacc[df][0], a, bb0);
                mma8(oacc[df][1], a, bb1);
            }
        }
        __syncwarp();   // Ps reads done before next tile's stores (intra-warp)
    }

    // ---- normalize (per-column l via shfl), stage Osf[d][n], store ----
    float invA = 1.0f / __shfl_sync(0xffffffffu, l0, 8 * q);
    float invB = 1.0f / __shfl_sync(0xffffffffu, l0, 8 * q + 4);
    float invC = 1.0f / __shfl_sync(0xffffffffu, l1, 8 * q);
    float invD = 1.0f / __shfl_sync(0xffffffffu, l1, 8 * q + 4);
    __syncthreads();   // all PV reads of Ps done before overwriting as Osf
    #pragma unroll
    for (int df = 0; df < 4; df++) {
        int d0 = df * 16 + g, d1 = d0 + 8;
        float2 p;
        p.x = oacc[df][0][0] * invA; p.y = oacc[df][0][1] * invB;
        *(float2*)&Osf[d0][rowb + 2 * q] = p;
        p.x = oacc[df][0][2] * invA; p.y = oacc[df][0][3] * invB;
        *(float2*)&Osf[d1][rowb + 2 * q] = p;
        p.x = oacc[df][1][0] * invC; p.y = oacc[df][1][1] * invD;
        *(float2*)&Osf[d0][rowb + 8 + 2 * q] = p;
        p.x = oacc[df][1][2] * invC; p.y = oacc[df][1][3] * invD;
        *(float2*)&Osf[d1][rowb + 8 + 2 * q] = p;
    }
    __syncthreads();
    {
        int d = t >> 2, nc = (t & 3) * 32;
        float* op = &Xatt[(size_t)b * Dd * NN + (size_t)(d * 4 + h) * NN + n0 + nc];
        #pragma unroll
        for (int u = 0; u < 8; u++)
            *(float4*)(op + u * 4) = *(const float4*)&Osf[d][nc + u * 4];
    }
}

// ---------------------------------------------------------------------------
extern "C" void kernel_launch(void* const* d_in, const int* in_sizes, int n_in,
                              void* d_out, int out_size)
{
    const float* desc0 = (const float*)d_in[0];
    const float* desc1 = (const float*)d_in[1];
    const float* M0    = (const float*)d_in[2];
    const float* M1    = (const float*)d_in[3];
    const float* Wq = (const float*)d_in[4];
    const float* bq = (const float*)d_in[5];
    const float* Wk = (const float*)d_in[6];
    const float* bk = (const float*)d_in[7];
    const float* Wv = (const float*)d_in[8];
    const float* bv = (const float*)d_in[9];
    const float* Wm = (const float*)d_in[10];
    const float* bm = (const float*)d_in[11];
    const float* W1 = (const float*)d_in[12];
    const float* b1 = (const float*)d_in[13];
    const float* g1 = (const float*)d_in[14];
    const float* be1 = (const float*)d_in[15];
    const float* W2 = (const float*)d_in[16];
    const float* b2 = (const float*)d_in[17];

    float* Dsc = (float*)d_out;   // [4, 256, 1024] — doubles as the output

    float *Q, *K, *V, *Xatt, *Y1, *W1c, *b1c;
    cudaGetSymbolAddress((void**)&Q,    g_Q);
    cudaGetSymbolAddress((void**)&K,    g_K);
    cudaGetSymbolAddress((void**)&V,    g_V);
    cudaGetSymbolAddress((void**)&Xatt, g_Xatt);
    cudaGetSymbolAddress((void**)&Y1,   g_Y1);
    cudaGetSymbolAddress((void**)&W1c,  g_W1c);
    cudaGetSymbolAddress((void**)&b1c,  g_b1c);

    static const int ATTN_SMEM = (128 * 68 + 2 * 64 * 72 + 2 * 64 * 68 + 64 * 136) * 4; // 141312
    static const int CPA_SMEM  = (3 * 64 * 36 + 3 * 32 * 136) * 4;                      // 79872
    cudaFuncSetAttribute(attn_mma,  cudaFuncAttributeMaxDynamicSharedMemorySize, ATTN_SMEM);
    cudaFuncSetAttribute(qkv_mma,   cudaFuncAttributeMaxDynamicSharedMemorySize, CPA_SMEM);
    cudaFuncSetAttribute(conv1_mma, cudaFuncAttributeMaxDynamicSharedMemorySize, CPA_SMEM);

    size_t descBytes = (size_t)2 * Dd * NN * sizeof(float);
    cudaMemcpyAsync(Dsc,               desc0, descBytes, cudaMemcpyDeviceToDevice, 0);
    cudaMemcpyAsync(Dsc + 2 * Dd * NN, desc1, descBytes, cudaMemcpyDeviceToDevice, 0);

    // One-shot composite-weight precompute (merge GEMM folded into conv1)
    copy_w1a<<<768, 256>>>(W1);
    compose_w1<<<dim3(4, 8, LL), 256>>>(W1, Wm);
    compose_b1<<<(LL * D2) / 256, 256>>>(W1, bm, b1);

    static const int crossFlag[LL] = {0, 1, 0, 1, 0, 1};

    for (int i = 0; i < LL; i++) {
        int xm = crossFlag[i] ? 2 : 0;
        const float* Wqi = Wq + (size_t)i * Dd * Dd;
        const float* bqi = bq + (size_t)i * Dd;
        const float* Wki = Wk + (size_t)i * Dd * Dd;
        const float* bki = bk + (size_t)i * Dd;
        const float* Wvi = Wv + (size_t)i * Dd * Dd;
        const float* bvi = bv + (size_t)i * Dd;
        const float* g1i = g1 + (size_t)i * D2;
        const float* be1i = be1 + (size_t)i * D2;
        const float* W2i = W2 + (size_t)i * Dd * D2;
        const float* b2i = b2 + (size_t)i * Dd;

        // Fused Q/K/V projections; block 0 zeroes BN accumulators for conv1
        qkv_mma<<<dim3(8, 12, 4), 256, CPA_SMEM>>>(Wqi, bqi, Wki, bki, Wvi, bvi,
                                                   Dsc, xm, Q, K, V);

        attn_mma<<<dim3(8, 16), 256, ATTN_SMEM>>>(Q, K, V, M0, M1, Xatt);

        // conv1 with composite weights on [Dsc ; Xatt]; BN stats fused in epilogue
        conv1_mma<<<dim3(8, 8, 4), 256, CPA_SMEM>>>(W1c + (size_t)i * D2 * D2,
                                                    b1c + (size_t)i * D2,
                                                    Dsc, Xatt, Y1);

        // conv2: per-block BN finalize (from accumulators) + BN+ReLU + residual
        conv_bnrelu<<<dim3(8, 4, 4), 256>>>(W2i, b2i, g1i, be1i, Y1, Dsc);
    }
}

// round 14
// speedup vs baseline: 1.0435x; 1.0435x over previous
#include <cuda_runtime.h>
#include <cstdint>

#define B4   4      // 2*BS concatenated batch
#define Dd   256    // feature dim
#define D2   512
#define NN   1024   // keypoints
#define LL   6

// Scratch (device globals; no allocation allowed)
__device__ float g_Q[B4 * Dd * NN];
__device__ float g_K[B4 * Dd * NN];
__device__ float g_V[B4 * Dd * NN];
__device__ float g_Xatt[B4 * Dd * NN];
__device__ float g_Y1[B4 * D2 * NN];
__device__ float g_bnsum[D2];
__device__ float g_bnsq[D2];
__device__ float g_W1c[LL * D2 * D2];   // composite [W1a | W1b@Wm] per layer
__device__ float g_b1c[LL * D2];        // composite b1 + W1b@bm

__device__ __forceinline__ uint32_t f2tf(float f) {
    uint32_t u; asm("cvt.rna.tf32.f32 %0, %1;" : "=r"(u) : "f"(f)); return u;
}
__device__ __forceinline__ void mma8(float c[4], const uint32_t a[4], const uint32_t b[2]) {
    asm volatile("mma.sync.aligned.m16n8k8.row.col.f32.tf32.tf32.f32 "
        "{%0,%1,%2,%3}, {%4,%5,%6,%7}, {%8,%9}, {%0,%1,%2,%3};"
        : "+f"(c[0]), "+f"(c[1]), "+f"(c[2]), "+f"(c[3])
        : "r"(a[0]), "r"(a[1]), "r"(a[2]), "r"(a[3]), "r"(b[0]), "r"(b[1]));
}
__device__ __forceinline__ void cp16(void* dst, const void* src) {
    uint32_t d = (uint32_t)__cvta_generic_to_shared(dst);
    asm volatile("cp.async.ca.shared.global [%0], [%1], 16;" :: "r"(d), "l"(src));
}

// ---------------------------------------------------------------------------
// cp.async 2-stage pipelined tf32 GEMM core, BK=32. Block 64(M) x 128(N),
// 256 threads (8 warps, 32x32 warp tile). A smem [m][k] stride 36 (frag bank
// 4g conflict-free), B smem [k][n] stride 136 (frag bank 8q+g conflict-free).
// Smem: 2*(64*36+32*136)*4 = 53248 B -> 3 blocks/SM.
// At the wait point only tile kt's group is pending (kt+1 is issued after the
// wait), so wait_group 0 == "wait for tile kt" while load(kt+1) still overlaps
// compute(kt).
// ---------------------------------------------------------------------------
template<int CONCAT>
__device__ __forceinline__ void gemm_core_cpa32(
    const float* __restrict__ Wp, int I,
    const float* __restrict__ XA, const float* __restrict__ XB,
    int col0, uint32_t (*As)[64][36], uint32_t (*Bs)[32][136],
    float acc[2][4][4])
{
    int t = threadIdx.x;
    int lane = t & 31, w = t >> 5;
    int g = lane >> 2, q = lane & 3;
    int warp_m = (w >> 2) * 32, warp_n = (w & 3) * 32;
    int ar = t >> 2, ak = (t & 3) * 8;   // A: 2x16B per thread
    int bk = t >> 4, bn = (t & 15) * 8;  // B: 4x16B per thread (k and k+16)

    auto issue = [&](int kt) {
        int buf = kt & 1;
        int k0 = kt << 5;
        const float* wr = &Wp[(size_t)ar * I + k0 + ak];
        cp16(&As[buf][ar][ak],     wr);
        cp16(&As[buf][ar][ak + 4], wr + 4);
        #pragma unroll
        for (int half = 0; half < 2; half++) {
            int ch = k0 + bk + half * 16;
            const float* src = XA; int chl = ch;
            if (CONCAT && ch >= 256) { src = XB; chl = ch - 256; }
            const float* gp = &src[(size_t)chl * NN + col0 + bn];
            cp16(&Bs[buf][bk + half * 16][bn],     gp);
            cp16(&Bs[buf][bk + half * 16][bn + 4], gp + 4);
        }
        asm volatile("cp.async.commit_group;" ::: "memory");
    };

    int nk = I >> 5;
    issue(0);

    for (int kt = 0; kt < nk; kt++) {
        asm volatile("cp.async.wait_group 0;" ::: "memory");   // tile kt landed
        __syncthreads();
        // prefetch next tile into the other buffer (its prior contents were
        // consumed at iter kt-1, which completed before this barrier)
        if (kt + 1 < nk) issue(kt + 1);
        int cur = kt & 1;
        #pragma unroll
        for (int ks = 0; ks < 32; ks += 8) {
            uint32_t bfr[4][2];
            #pragma unroll
            for (int nt = 0; nt < 4; nt++) {
                int n = warp_n + nt * 8 + g;
                bfr[nt][0] = Bs[cur][ks + q][n];
                bfr[nt][1] = Bs[cur][ks + q + 4][n];
            }
            #pragma unroll
            for (int mt = 0; mt < 2; mt++) {
                int m = warp_m + mt * 16 + g;
                uint32_t a[4];
                a[0] = As[cur][m][ks + q];
                a[1] = As[cur][m + 8][ks + q];
                a[2] = As[cur][m][ks + q + 4];
                a[3] = As[cur][m + 8][ks + q + 4];
                #pragma unroll
                for (int nt = 0; nt < 4; nt++)
                    mma8(acc[mt][nt], a, bfr[nt]);
            }
        }
    }
}

// Register-staged double-buffered BK=16 core with BN+ReLU transform on the
// B-load path; scale/shift come from a block-local smem table.
__device__ __forceinline__ void gemm_core_bnrelu(
    const float* __restrict__ Wp, int I,
    const float* __restrict__ XA,
    int col0, uint32_t (*As)[64][20], uint32_t (*Bs)[16][136],
    const float* __restrict__ sSc, const float* __restrict__ sSh,
    float acc[2][4][4])
{
    int t = threadIdx.x;
    int lane = t & 31, w = t >> 5;
    int g = lane >> 2, q = lane & 3;
    int warp_m = (w >> 2) * 32, warp_n = (w & 3) * 32;
    int ar = t >> 2, ak = (t & 3) * 4;
    int bk = t >> 4, bn = (t & 15) * 8;

    float4 aReg;
    float4 bReg[2];
    float bSc = 0.f, bSh = 0.f;

    auto load_tile = [&](int k0) {
        aReg = *(const float4*)&Wp[(size_t)ar * I + k0 + ak];
        int ch = k0 + bk;
        const float* gp = &XA[(size_t)ch * NN + col0 + bn];
        bSc = sSc[ch]; bSh = sSh[ch];
        bReg[0] = *(const float4*)gp;
        bReg[1] = *(const float4*)(gp + 4);
    };
    auto store_tile = [&](int buf) {
        uint4 s;
        s.x = f2tf(aReg.x); s.y = f2tf(aReg.y);
        s.z = f2tf(aReg.z); s.w = f2tf(aReg.w);
        *(uint4*)&As[buf][ar][ak] = s;
        #pragma unroll
        for (int u = 0; u < 2; u++) {
            float4 xv = bReg[u];
            xv.x = fmaxf(fmaf(xv.x, bSc, bSh), 0.f);
            xv.y = fmaxf(fmaf(xv.y, bSc, bSh), 0.f);
            xv.z = fmaxf(fmaf(xv.z, bSc, bSh), 0.f);
            xv.w = fmaxf(fmaf(xv.w, bSc, bSh), 0.f);
            uint4 o;
            o.x = f2tf(xv.x); o.y = f2tf(xv.y);
            o.z = f2tf(xv.z); o.w = f2tf(xv.w);
            *(uint4*)&Bs[buf][bk][bn + u * 4] = o;
        }
    };

    int nk = I >> 4;
    load_tile(0);
    store_tile(0);
    __syncthreads();

    for (int kt = 0; kt < nk; kt++) {
        int cur = kt & 1;
        if (kt + 1 < nk) load_tile((kt + 1) << 4);
        #pragma unroll
        for (int ks = 0; ks < 16; ks += 8) {
            uint32_t bfr[4][2];
            #pragma unroll
            for (int nt = 0; nt < 4; nt++) {
                int n = warp_n + nt * 8 + g;
                bfr[nt][0] = Bs[cur][ks + q][n];
                bfr[nt][1] = Bs[cur][ks + q + 4][n];
            }
            #pragma unroll
            for (int mt = 0; mt < 2; mt++) {
                int m = warp_m + mt * 16 + g;
                uint32_t a[4];
                a[0] = As[cur][m][ks + q];
                a[1] = As[cur][m + 8][ks + q];
                a[2] = As[cur][m][ks + q + 4];
                a[3] = As[cur][m + 8][ks + q + 4];
                #pragma unroll
                for (int nt = 0; nt < 4; nt++)
                    mma8(acc[mt][nt], a, bfr[nt]);
            }
        }
        if (kt + 1 < nk) store_tile(cur ^ 1);
        __syncthreads();
    }
}

// Epilogue; STATS=1 additionally accumulates per-channel sum/sumsq into
// g_bnsum/g_bnsq (quad shfl-reduce, then atomicAdd from lane q==0).
template<int STATS>
__device__ __forceinline__ void gemm_epilogue(
    float acc[2][4][4], const float* __restrict__ bias,
    float* __restrict__ Ob, int row0, int col0, int addOut)
{
    int t = threadIdx.x; int lane = t & 31; int w = t >> 5;
    int g = lane >> 2, q = lane & 3;
    int warp_m = (w >> 2) * 32, warp_n = (w & 3) * 32;
    #pragma unroll
    for (int mt = 0; mt < 2; mt++) {
        #pragma unroll
        for (int half = 0; half < 2; half++) {
            int r = row0 + warp_m + mt * 16 + g + half * 8;
            float bb = bias[r];
            float rs = 0.f, rq = 0.f;
            #pragma unroll
            for (int nt = 0; nt < 4; nt++) {
                int c = col0 + warp_n + nt * 8 + 2 * q;
                float* p = &Ob[(size_t)r * NN + c];
                float v0 = acc[mt][nt][half * 2 + 0] + bb;
                float v1 = acc[mt][nt][half * 2 + 1] + bb;
                if (addOut) { float2 e = *(const float2*)p; v0 += e.x; v1 += e.y; }
                float2 o; o.x = v0; o.y = v1;
                *(float2*)p = o;
                if (STATS) { rs += v0 + v1; rq += v0 * v0 + v1 * v1; }
            }
            if (STATS) {
                rs += __shfl_xor_sync(0xffffffffu, rs, 1);
                rs += __shfl_xor_sync(0xffffffffu, rs, 2);
                rq += __shfl_xor_sync(0xffffffffu, rq, 1);
                rq += __shfl_xor_sync(0xffffffffu, rq, 2);
                if (q == 0) {
                    atomicAdd(&g_bnsum[r], rs);
                    atomicAdd(&g_bnsq[r], rq);
                }
            }
        }
    }
}

// Fused Q/K/V projection: logical rows 0-255 = Q, 256-511 = K, 512-767 = V.
// Block (0,0,0) also re-zeroes the BN accumulators for this layer's conv1.
__global__ __launch_bounds__(256, 3) void qkv_mma(
    const float* __restrict__ Wq, const float* __restrict__ bq,
    const float* __restrict__ Wk, const float* __restrict__ bk,
    const float* __restrict__ Wv, const float* __restrict__ bv,
    const float* __restrict__ X, int xorMask,
    float* __restrict__ Qo, float* __restrict__ Ko, float* __restrict__ Vo)
{
    extern __shared__ uint32_t sm[];
    uint32_t (*As)[64][36]  = (uint32_t(*)[64][36])sm;
    uint32_t (*Bs)[32][136] = (uint32_t(*)[32][136])(sm + 2 * 64 * 36);
    int b    = blockIdx.z;
    int row0 = blockIdx.y * 64;
    int col0 = blockIdx.x * 128;
    if (blockIdx.x == 0 && blockIdx.y == 0 && blockIdx.z == 0) {
        int t = threadIdx.x;
        g_bnsum[t] = 0.f; g_bnsum[t + 256] = 0.f;
        g_bnsq[t]  = 0.f; g_bnsq[t + 256]  = 0.f;
    }
    int sel  = row0 >> 8;
    int lrow0 = row0 & 255;
    const float* W; const float* bias; float* Out; int xb;
    if (sel == 0)      { W = Wq; bias = bq; Out = Qo; xb = b; }
    else if (sel == 1) { W = Wk; bias = bk; Out = Ko; xb = b ^ xorMask; }
    else               { W = Wv; bias = bv; Out = Vo; xb = b ^ xorMask; }
    const float* XA = X + (size_t)xb * Dd * NN;
    float acc[2][4][4] = {};
    gemm_core_cpa32<0>(W + (size_t)lrow0 * Dd, Dd, XA, nullptr, col0, As, Bs, acc);
    gemm_epilogue<0>(acc, bias, Out + (size_t)b * Dd * NN, lrow0, col0, 0);
}

// conv1 on [X ; X2] with composite weights; accumulates BN stats.
__global__ __launch_bounds__(256, 3) void conv1_mma(
    const float* __restrict__ W, const float* __restrict__ bias,
    const float* __restrict__ X, const float* __restrict__ X2,
    float* __restrict__ Out)
{
    extern __shared__ uint32_t sm[];
    uint32_t (*As)[64][36]  = (uint32_t(*)[64][36])sm;
    uint32_t (*Bs)[32][136] = (uint32_t(*)[32][136])(sm + 2 * 64 * 36);
    int b    = blockIdx.z;
    int row0 = blockIdx.y * 64;
    int col0 = blockIdx.x * 128;
    const float* XA = X + (size_t)b * 256 * NN;
    const float* XB = X2 + (size_t)b * 256 * NN;
    float acc[2][4][4] = {};
    gemm_core_cpa32<1>(W + (size_t)row0 * D2, D2, XA, XB, col0, As, Bs, acc);
    gemm_epilogue<1>(acc, bias, Out + (size_t)b * D2 * NN, row0, col0, 0);
}

// conv2: recomputes BN scale/shift per block from accumulators, then GEMM
// with fused BN+ReLU on the B path (+residual into Dsc).
__global__ __launch_bounds__(256, 2) void conv_bnrelu(
    const float* __restrict__ W, const float* __restrict__ bias,
    const float* __restrict__ gvec, const float* __restrict__ betav,
    const float* __restrict__ X, float* __restrict__ Out)
{
    __shared__ uint32_t As[2][64][20];
    __shared__ uint32_t Bs[2][16][136];
    __shared__ float sSc[D2], sSh[D2];
    int t = threadIdx.x;
    #pragma unroll
    for (int u = 0; u < 2; u++) {
        int c = t + u * 256;
        float s = g_bnsum[c], sq = g_bnsq[c];
        float mean = s * (1.0f / 4096.0f);
        float var  = sq * (1.0f / 4096.0f) - mean * mean;
        float rstd = rsqrtf(var + 1e-5f);
        float sc = gvec[c] * rstd;
        sSc[c] = sc;
        sSh[c] = betav[c] - mean * sc;
    }
    __syncthreads();
    int b    = blockIdx.z;
    int row0 = blockIdx.y * 64;
    int col0 = blockIdx.x * 128;
    const float* XA = X + (size_t)b * (size_t)D2 * NN;
    float acc[2][4][4] = {};
    gemm_core_bnrelu(W + (size_t)row0 * D2, D2, XA, col0, As, Bs, sSc, sSh, acc);
    gemm_epilogue<0>(acc, bias, Out + (size_t)b * Dd * NN, row0, col0, 1);
}

// ---------------------------------------------------------------------------
// Composite-weight precompute (once per launch).
// ---------------------------------------------------------------------------
__global__ __launch_bounds__(256) void copy_w1a(const float* __restrict__ W1)
{
    size_t i = (size_t)blockIdx.x * 256 + threadIdx.x;   // float4 index
    int l   = (int)(i / (D2 * 64));
    int rem = (int)(i % (D2 * 64));
    int r = rem >> 6, c4 = (rem & 63) * 4;
    *(float4*)&g_W1c[(size_t)l * D2 * D2 + (size_t)r * D2 + c4] =
        *(const float4*)&W1[(size_t)l * D2 * D2 + (size_t)r * D2 + c4];
}

__global__ __launch_bounds__(256) void compose_w1(
    const float* __restrict__ W1, const float* __restrict__ Wm)
{
    __shared__ float Asm[64][17];   // [row][k]
    __shared__ float Bsm[16][68];   // [k][col]
    int l = blockIdx.z;
    int row0 = blockIdx.y * 64;
    int col0 = blockIdx.x * 64;
    const float* W1l = W1 + (size_t)l * D2 * D2;
    const float* Wml = Wm + (size_t)l * Dd * Dd;
    float* Out = g_W1c + (size_t)l * D2 * D2;
    int t = threadIdx.x; int tx = t & 15, ty = t >> 4;
    float acc[4][4] = {};
    for (int k0 = 0; k0 < 256; k0 += 16) {
        int lr = t >> 2, lk = (t & 3) * 4;
        float4 wv = *(const float4*)&W1l[(size_t)(row0 + lr) * D2 + 256 + k0 + lk];
        Asm[lr][lk + 0] = wv.x; Asm[lr][lk + 1] = wv.y;
        Asm[lr][lk + 2] = wv.z; Asm[lr][lk + 3] = wv.w;
        float4 xv = *(const float4*)&Wml[(size_t)(k0 + (t >> 4)) * Dd + col0 + (t & 15) * 4];
        *(float4*)&Bsm[t >> 4][(t & 15) * 4] = xv;
        __syncthreads();
        #pragma unroll
        for (int k = 0; k < 16; k++) {
            float a0 = Asm[ty * 4 + 0][k], a1 = Asm[ty * 4 + 1][k];
            float a2 = Asm[ty * 4 + 2][k], a3 = Asm[ty * 4 + 3][k];
            float4 bv = *(const float4*)&Bsm[k][tx * 4];
            acc[0][0] += a0 * bv.x; acc[0][1] += a0 * bv.y; acc[0][2] += a0 * bv.z; acc[0][3] += a0 * bv.w;
            acc[1][0] += a1 * bv.x; acc[1][1] += a1 * bv.y; acc[1][2] += a1 * bv.z; acc[1][3] += a1 * bv.w;
            acc[2][0] += a2 * bv.x; acc[2][1] += a2 * bv.y; acc[2][2] += a2 * bv.z; acc[2][3] += a2 * bv.w;
            acc[3][0] += a3 * bv.x; acc[3][1] += a3 * bv.y; acc[3][2] += a3 * bv.z; acc[3][3] += a3 * bv.w;
        }
        __syncthreads();
    }
    #pragma unroll
    for (int i = 0; i < 4; i++)
        #pragma unroll
        for (int j = 0; j < 4; j++)
            Out[(size_t)(row0 + ty * 4 + i) * D2 + 256 + col0 + tx * 4 + j] = acc[i][j];
}

__global__ __launch_bounds__(256) void compose_b1(
    const float* __restrict__ W1, const float* __restrict__ bm,
    const float* __restrict__ b1)
{
    int i = blockIdx.x * 256 + threadIdx.x;   // LL*D2
    int l = i >> 9, o = i & 511;
    const float* wrow = W1 + (size_t)l * D2 * D2 + (size_t)o * D2 + 256;
    const float* bml = bm + (size_t)l * Dd;
    float s = b1[(size_t)l * D2 + o];
    for (int c = 0; c < 256; c++) s += wrow[c] * bml[c];
    g_b1c[i] = s;
}

// ---------------------------------------------------------------------------
// Flash attention, tf32 mma, cp.async double-buffered K/V, transposed PV.
// Br=64 x Bc=64, 128 threads (4 warps; warp w owns q-rows [16w,16w+16)).
// Q pre-scaled by 1/8 at smem store (exact).
// ---------------------------------------------------------------------------
__global__ __launch_bounds__(128) void attn_mma(
    const float* __restrict__ Q, const float* __restrict__ K,
    const float* __restrict__ V,
    const float* __restrict__ M0, const float* __restrict__ M1,
    float* __restrict__ Xatt)
{
    extern __shared__ uint32_t smu[];
    uint32_t (*Qs)[68]     = (uint32_t(*)[68])smu;                               // [n][d]
    uint32_t (*Ks)[64][72] = (uint32_t(*)[64][72])(smu + 64 * 68);               // 2x [d][m]
    uint32_t (*Vs)[64][68] = (uint32_t(*)[64][68])(smu + 64 * 68 + 2 * 64 * 72); // 2x [d][m]
    uint32_t (*Ps)[72]     = (uint32_t(*)[72])(smu + 64 * 68 + 2 * 64 * 72 + 2 * 64 * 68); // [m][n]
    float    (*Osf)[72]    = (float(*)[72])Ps;

    int bh = blockIdx.y; int b = bh >> 2, h = bh & 3;
    int n0 = blockIdx.x * 64;
    int t = threadIdx.x;
    int lane = t & 31, w = t >> 5;
    int g = lane >> 2, q = lane & 3;
    int rowb = w * 16;

    const float* Qb = Q + (size_t)b * Dd * NN;
    const float* Kb = K + (size_t)b * Dd * NN;
    const float* Vb = V + (size_t)b * Dd * NN;
    const float* Mb = (b < 2) ? M0 + (size_t)b * NN * NN
                              : M1 + (size_t)(b - 2) * NN * NN;

    // Q tile transpose-load -> Qs[n][d], pre-scaled by 1/8 (exact)
    {
        int d = t >> 1, nc = (t & 1) * 32;
        const float* gp = &Qb[(size_t)(d * 4 + h) * NN + n0 + nc];
        #pragma unroll
        for (int u = 0; u < 8; u++) {
            float4 v = *(const float4*)(gp + u * 4);
            Qs[nc + u * 4 + 0][d] = __float_as_uint(v.x * 0.125f);
            Qs[nc + u * 4 + 1][d] = __float_as_uint(v.y * 0.125f);
            Qs[nc + u * 4 + 2][d] = __float_as_uint(v.z * 0.125f);
            Qs[nc + u * 4 + 3][d] = __float_as_uint(v.w * 0.125f);
        }
    }

    auto issue_kv = [&](int it) {
        int buf = it & 1, mt = it << 6;
        #pragma unroll
        for (int u = 0; u < 8; u++) {
            int cr = u * 8 + (t >> 4);
            int cc = (t & 15) * 4;
            cp16(&Ks[buf][cr][cc], &Kb[(size_t)(cr * 4 + h) * NN + mt + cc]);
            cp16(&Vs[buf][cr][cc], &Vb[(size_t)(cr * 4 + h) * NN + mt + cc]);
        }
        asm volatile("cp.async.commit_group;" ::: "memory");
    };

    float oacc[4][2][4] = {};
    float m0r = -1e30f, m1r = -1e30f, l0 = 0.f, l1 = 0.f;
    int r0g = n0 + rowb + g, r1g = r0g + 8;

    issue_kv(0);

    for (int it = 0; it < 16; it++) {
        int buf = it & 1, mt = it << 6;
        asm volatile("cp.async.wait_group 0;" ::: "memory");
        __syncthreads();
        if (it + 1 < 16) issue_kv(it + 1);

        float sacc[8][4] = {};
        #pragma unroll
        for (int ks = 0; ks < 8; ks++) {
            int kk = ks * 8;
            uint32_t a[4];
            a[0] = Qs[rowb + g][kk + q];
            a[1] = Qs[rowb + g + 8][kk + q];
            a[2] = Qs[rowb + g][kk + q + 4];
            a[3] = Qs[rowb + g + 8][kk + q + 4];
            #pragma unroll
            for (int nf = 0; nf < 8; nf++) {
                uint32_t bb[2];
                bb[0] = Ks[buf][kk + q][nf * 8 + g];
                bb[1] = Ks[buf][kk + q + 4][nf * 8 + g];
                mma8(sacc[nf], a, bb);
            }
        }

        const float* mr0 = Mb + (size_t)r0g * NN + mt;
        const float* mr1 = Mb + (size_t)r1g * NN + mt;
        float v0[16], v1[16];
        float rm0 = -1e30f, rm1 = -1e30f;
        #pragma unroll
        for (int nf = 0; nf < 8; nf++) {
            int c = nf * 8 + 2 * q;
            float2 k0v = *(const float2*)&mr0[c];
            float2 k1v = *(const float2*)&mr1[c];
            v0[2 * nf]     = sacc[nf][0] * k0v.x;
            v0[2 * nf + 1] = sacc[nf][1] * k0v.y;
            v1[2 * nf]     = sacc[nf][2] * k1v.x;
            v1[2 * nf + 1] = sacc[nf][3] * k1v.y;
            rm0 = fmaxf(rm0, fmaxf(v0[2 * nf], v0[2 * nf + 1]));
            rm1 = fmaxf(rm1, fmaxf(v1[2 * nf], v1[2 * nf + 1]));
        }
        rm0 = fmaxf(rm0, __shfl_xor_sync(0xffffffffu, rm0, 1));
        rm0 = fmaxf(rm0, __shfl_xor_sync(0xffffffffu, rm0, 2));
        rm1 = fmaxf(rm1, __shfl_xor_sync(0xffffffffu, rm1, 1));
        rm1 = fmaxf(rm1, __shfl_xor_sync(0xffffffffu, rm1, 2));
        float nm0 = fmaxf(m0r, rm0), nm1 = fmaxf(m1r, rm1);
        float rs0 = 0.f, rs1 = 0.f;
        #pragma unroll
        for (int i = 0; i < 16; i++) {
            v0[i] = __expf(v0[i] - nm0); rs0 += v0[i];
            v1[i] = __expf(v1[i] - nm1); rs1 += v1[i];
        }
        rs0 += __shfl_xor_sync(0xffffffffu, rs0, 1);
        rs0 += __shfl_xor_sync(0xffffffffu, rs0, 2);
        rs1 += __shfl_xor_sync(0xffffffffu, rs1, 1);
        rs1 += __shfl_xor_sync(0xffffffffu, rs1, 2);
        float f0 = __expf(m0r - nm0), f1 = __expf(m1r - nm1);
        m0r = nm0; m1r = nm1;
        l0 = l0 * f0 + rs0;
        l1 = l1 * f1 + rs1;

        {
            float fA = __shfl_sync(0xffffffffu, f0, 8 * q);
            float fB = __shfl_sync(0xffffffffu, f0, 8 * q + 4);
            float fC = __shfl_sync(0xffffffffu, f1, 8 * q);
            float fD = __shfl_sync(0xffffffffu, f1, 8 * q + 4);
            #pragma unroll
            for (int df = 0; df < 4; df++) {
                oacc[df][0][0] *= fA; oacc[df][0][1] *= fB;
                oacc[df][0][2] *= fA; oacc[df][0][3] *= fB;
                oacc[df][1][0] *= fC; oacc[df][1][1] *= fD;
                oacc[df][1][2] *= fC; oacc[df][1][3] *= fD;
            }
        }

        #pragma unroll
        for (int nf = 0; nf < 8; nf++) {
            Ps[nf * 8 + 2 * q][rowb + g]         = __float_as_uint(v0[2 * nf]);
            Ps[nf * 8 + 2 * q + 1][rowb + g]     = __float_as_uint(v0[2 * nf + 1]);
            Ps[nf * 8 + 2 * q][rowb + g + 8]     = __float_as_uint(v1[2 * nf]);
            Ps[nf * 8 + 2 * q + 1][rowb + g + 8] = __float_as_uint(v1[2 * nf + 1]);
        }
        __syncwarp();

        #pragma unroll
        for (int ks = 0; ks < 8; ks++) {
            int kk = ks * 8;
            uint32_t bb0[2], bb1[2];
            bb0[0] = Ps[kk + q][rowb + g];
            bb0[1] = Ps[kk + q + 4][rowb + g];
            bb1[0] = Ps[kk + q][rowb + 8 + g];
            bb1[1] = Ps[kk + q + 4][rowb + 8 + g];
            #pragma unroll
            for (int df = 0; df < 4; df++) {
                uint32_t a[4];
                a[0] = Vs[buf][df * 16 + g][kk + q];
                a[1] = Vs[buf][df * 16 + 8 + g][kk + q];
                a[2] = Vs[buf][df * 16 + g][kk + q + 4];
                a[3] = Vs[buf][df * 16 + 8 + g][kk + q + 4];
                mma8(oacc[df][0], a, bb0);
                mma8(oacc[df][1], a, bb1);
            }
        }
        __syncwarp();
    }

    float invA = 1.0f / __shfl_sync(0xffffffffu, l0, 8 * q);
    float invB = 1.0f / __shfl_sync(0xffffffffu, l0, 8 * q + 4);
    float invC = 1.0f / __shfl_sync(0xffffffffu, l1, 8 * q);
    float invD = 1.0f / __shfl_sync(0xffffffffu, l1, 8 * q + 4);
    __syncthreads();
    #pragma unroll
    for (int df = 0; df < 4; df++) {
        int d0 = df * 16 + g, d1 = d0 + 8;
        float2 p;
        p.x = oacc[df][0][0] * invA; p.y = oacc[df][0][1] * invB;
        *(float2*)&Osf[d0][rowb + 2 * q] = p;
        p.x = oacc[df][0][2] * invA; p.y = oacc[df][0][3] * invB;
        *(float2*)&Osf[d1][rowb + 2 * q] = p;
        p.x = oacc[df][1][0] * invC; p.y = oacc[df][1][1] * invD;
        *(float2*)&Osf[d0][rowb + 8 + 2 * q] = p;
        p.x = oacc[df][1][2] * invC; p.y = oacc[df][1][3] * invD;
        *(float2*)&Osf[d1][rowb + 8 + 2 * q] = p;
    }
    __syncthreads();
    {
        int d = t >> 1, nc = (t & 1) * 32;
        float* op = &Xatt[(size_t)b * Dd * NN + (size_t)(d * 4 + h) * NN + n0 + nc];
        #pragma unroll
        for (int u = 0; u < 8; u++)
            *(float4*)(op + u * 4) = *(const float4*)&Osf[d][nc + u * 4];
    }
}

// ---------------------------------------------------------------------------
extern "C" void kernel_launch(void* const* d_in, const int* in_sizes, int n_in,
                              void* d_out, int out_size)
{
    const float* desc0 = (const float*)d_in[0];
    const float* desc1 = (const float*)d_in[1];
    const float* M0    = (const float*)d_in[2];
    const float* M1    = (const float*)d_in[3];
    const float* Wq = (const float*)d_in[4];
    const float* bq = (const float*)d_in[5];
    const float* Wk = (const float*)d_in[6];
    const float* bk = (const float*)d_in[7];
    const float* Wv = (const float*)d_in[8];
    const float* bv = (const float*)d_in[9];
    const float* Wm = (const float*)d_in[10];
    const float* bm = (const float*)d_in[11];
    const float* W1 = (const float*)d_in[12];
    const float* b1 = (const float*)d_in[13];
    const float* g1 = (const float*)d_in[14];
    const float* be1 = (const float*)d_in[15];
    const float* W2 = (const float*)d_in[16];
    const float* b2 = (const float*)d_in[17];

    float* Dsc = (float*)d_out;   // [4, 256, 1024] — doubles as the output

    float *Q, *K, *V, *Xatt, *Y1, *W1c, *b1c;
    cudaGetSymbolAddress((void**)&Q,    g_Q);
    cudaGetSymbolAddress((void**)&K,    g_K);
    cudaGetSymbolAddress((void**)&V,    g_V);
    cudaGetSymbolAddress((void**)&Xatt, g_Xatt);
    cudaGetSymbolAddress((void**)&Y1,   g_Y1);
    cudaGetSymbolAddress((void**)&W1c,  g_W1c);
    cudaGetSymbolAddress((void**)&b1c,  g_b1c);

    static const int ATTN_SMEM = (64 * 68 + 2 * 64 * 72 + 2 * 64 * 68 + 64 * 72) * 4; // 107520
    static const int CPA_SMEM  = (2 * 64 * 36 + 2 * 32 * 136) * 4;                    // 53248
    cudaFuncSetAttribute(attn_mma,  cudaFuncAttributeMaxDynamicSharedMemorySize, ATTN_SMEM);
    cudaFuncSetAttribute(qkv_mma,   cudaFuncAttributeMaxDynamicSharedMemorySize, CPA_SMEM);
    cudaFuncSetAttribute(conv1_mma, cudaFuncAttributeMaxDynamicSharedMemorySize, CPA_SMEM);

    size_t descBytes = (size_t)2 * Dd * NN * sizeof(float);
    cudaMemcpyAsync(Dsc,               desc0, descBytes, cudaMemcpyDeviceToDevice, 0);
    cudaMemcpyAsync(Dsc + 2 * Dd * NN, desc1, descBytes, cudaMemcpyDeviceToDevice, 0);

    // One-shot composite-weight precompute (merge GEMM folded into conv1)
    copy_w1a<<<768, 256>>>(W1);
    compose_w1<<<dim3(4, 8, LL), 256>>>(W1, Wm);
    compose_b1<<<(LL * D2) / 256, 256>>>(W1, bm, b1);

    static const int crossFlag[LL] = {0, 1, 0, 1, 0, 1};

    for (int i = 0; i < LL; i++) {
        int xm = crossFlag[i] ? 2 : 0;
        const float* Wqi = Wq + (size_t)i * Dd * Dd;
        const float* bqi = bq + (size_t)i * Dd;
        const float* Wki = Wk + (size_t)i * Dd * Dd;
        const float* bki = bk + (size_t)i * Dd;
        const float* Wvi = Wv + (size_t)i * Dd * Dd;
        const float* bvi = bv + (size_t)i * Dd;
        const float* g1i = g1 + (size_t)i * D2;
        const float* be1i = be1 + (size_t)i * D2;
        const float* W2i = W2 + (size_t)i * Dd * D2;
        const float* b2i = b2 + (size_t)i * Dd;

        // Fused Q/K/V projections; block 0 zeroes BN accumulators for conv1
        qkv_mma<<<dim3(8, 12, 4), 256, CPA_SMEM>>>(Wqi, bqi, Wki, bki, Wvi, bvi,
                                                   Dsc, xm, Q, K, V);

        attn_mma<<<dim3(16, 16), 128, ATTN_SMEM>>>(Q, K, V, M0, M1, Xatt);

        // conv1 with composite weights on [Dsc ; Xatt]; BN stats fused in epilogue
        conv1_mma<<<dim3(8, 8, 4), 256, CPA_SMEM>>>(W1c + (size_t)i * D2 * D2,
                                                    b1c + (size_t)i * D2,
                                                    Dsc, Xatt, Y1);

        // conv2: per-block BN finalize (from accumulators) + BN+ReLU + residual
        conv_bnrelu<<<dim3(8, 4, 4), 256>>>(W2i, b2i, g1i, be1i, Y1, Dsc);
    }
}

// round 15
// speedup vs baseline: 1.0447x; 1.0011x over previous
#include <cuda_runtime.h>
#include <cstdint>

#define B4   4      // 2*BS concatenated batch
#define Dd   256    // feature dim
#define D2   512
#define NN   1024   // keypoints
#define LL   6

// Scratch (device globals; no allocation allowed)
__device__ float g_Q[B4 * Dd * NN];
__device__ float g_K[B4 * Dd * NN];
__device__ float g_V[B4 * Dd * NN];
__device__ float g_Xatt[B4 * Dd * NN];
__device__ float g_Y1[B4 * D2 * NN];
__device__ float g_bnsum[D2];
__device__ float g_bnsq[D2];
__device__ float g_W1c[LL * D2 * D2];   // composite [W1a | W1b@Wm] per layer
__device__ float g_b1c[LL * D2];        // composite b1 + W1b@bm

__device__ __forceinline__ uint32_t f2tf(float f) {
    uint32_t u; asm("cvt.rna.tf32.f32 %0, %1;" : "=r"(u) : "f"(f)); return u;
}
__device__ __forceinline__ void mma8(float c[4], const uint32_t a[4], const uint32_t b[2]) {
    asm volatile("mma.sync.aligned.m16n8k8.row.col.f32.tf32.tf32.f32 "
        "{%0,%1,%2,%3}, {%4,%5,%6,%7}, {%8,%9}, {%0,%1,%2,%3};"
        : "+f"(c[0]), "+f"(c[1]), "+f"(c[2]), "+f"(c[3])
        : "r"(a[0]), "r"(a[1]), "r"(a[2]), "r"(a[3]), "r"(b[0]), "r"(b[1]));
}
__device__ __forceinline__ void cp16(void* dst, const void* src) {
    uint32_t d = (uint32_t)__cvta_generic_to_shared(dst);
    asm volatile("cp.async.ca.shared.global [%0], [%1], 16;" :: "r"(d), "l"(src));
}

// ---------------------------------------------------------------------------
// cp.async 3-stage pipelined tf32 GEMM core, BK=32. Block 64(M) x 128(N),
// 256 threads (8 warps, 32x32 warp tile). A smem [m][k] stride 36 (frag bank
// 4g conflict-free), B smem [k][n] stride 136 (frag bank 8q+g conflict-free).
// ---------------------------------------------------------------------------
template<int CONCAT>
__device__ __forceinline__ void gemm_core_cpa32(
    const float* __restrict__ Wp, int I,
    const float* __restrict__ XA, const float* __restrict__ XB,
    int col0, uint32_t (*As)[64][36], uint32_t (*Bs)[32][136],
    float acc[2][4][4])
{
    int t = threadIdx.x;
    int lane = t & 31, w = t >> 5;
    int g = lane >> 2, q = lane & 3;
    int warp_m = (w >> 2) * 32, warp_n = (w & 3) * 32;
    int ar = t >> 2, ak = (t & 3) * 8;   // A: 2x16B per thread
    int bk = t >> 4, bn = (t & 15) * 8;  // B: 4x16B per thread (k and k+16)

    auto issue = [&](int kt) {
        int buf = kt % 3;
        int k0 = kt << 5;
        const float* wr = &Wp[(size_t)ar * I + k0 + ak];
        cp16(&As[buf][ar][ak],     wr);
        cp16(&As[buf][ar][ak + 4], wr + 4);
        #pragma unroll
        for (int half = 0; half < 2; half++) {
            int ch = k0 + bk + half * 16;
            const float* src = XA; int chl = ch;
            if (CONCAT && ch >= 256) { src = XB; chl = ch - 256; }
            const float* gp = &src[(size_t)chl * NN + col0 + bn];
            cp16(&Bs[buf][bk + half * 16][bn],     gp);
            cp16(&Bs[buf][bk + half * 16][bn + 4], gp + 4);
        }
        asm volatile("cp.async.commit_group;" ::: "memory");
    };

    int nk = I >> 5;
    issue(0);
    if (nk > 1) issue(1);

    for (int kt = 0; kt < nk; kt++) {
        if (kt + 1 < nk) asm volatile("cp.async.wait_group 1;" ::: "memory");
        else             asm volatile("cp.async.wait_group 0;" ::: "memory");
        __syncthreads();
        int cur = kt % 3;
        #pragma unroll
        for (int ks = 0; ks < 32; ks += 8) {
            uint32_t bfr[4][2];
            #pragma unroll
            for (int nt = 0; nt < 4; nt++) {
                int n = warp_n + nt * 8 + g;
                bfr[nt][0] = Bs[cur][ks + q][n];
                bfr[nt][1] = Bs[cur][ks + q + 4][n];
            }
            #pragma unroll
            for (int mt = 0; mt < 2; mt++) {
                int m = warp_m + mt * 16 + g;
                uint32_t a[4];
                a[0] = As[cur][m][ks + q];
                a[1] = As[cur][m + 8][ks + q];
                a[2] = As[cur][m][ks + q + 4];
                a[3] = As[cur][m + 8][ks + q + 4];
                #pragma unroll
                for (int nt = 0; nt < 4; nt++)
                    mma8(acc[mt][nt], a, bfr[nt]);
            }
        }
        // issue(kt+2) writes buf (kt-1)%3, consumed at iter kt-1 (done before
        // this iteration's barrier) -> safe.
        if (kt + 2 < nk) issue(kt + 2);
    }
}

// Register-staged double-buffered BK=16 core with BN+ReLU transform on the
// B-load path; scale/shift come from a block-local smem table.
__device__ __forceinline__ void gemm_core_bnrelu(
    const float* __restrict__ Wp, int I,
    const float* __restrict__ XA,
    int col0, uint32_t (*As)[64][20], uint32_t (*Bs)[16][136],
    const float* __restrict__ sSc, const float* __restrict__ sSh,
    float acc[2][4][4])
{
    int t = threadIdx.x;
    int lane = t & 31, w = t >> 5;
    int g = lane >> 2, q = lane & 3;
    int warp_m = (w >> 2) * 32, warp_n = (w & 3) * 32;
    int ar = t >> 2, ak = (t & 3) * 4;
    int bk = t >> 4, bn = (t & 15) * 8;

    float4 aReg;
    float4 bReg[2];
    float bSc = 0.f, bSh = 0.f;

    auto load_tile = [&](int k0) {
        aReg = *(const float4*)&Wp[(size_t)ar * I + k0 + ak];
        int ch = k0 + bk;
        const float* gp = &XA[(size_t)ch * NN + col0 + bn];
        bSc = sSc[ch]; bSh = sSh[ch];
        bReg[0] = *(const float4*)gp;
        bReg[1] = *(const float4*)(gp + 4);
    };
    auto store_tile = [&](int buf) {
        uint4 s;
        s.x = f2tf(aReg.x); s.y = f2tf(aReg.y);
        s.z = f2tf(aReg.z); s.w = f2tf(aReg.w);
        *(uint4*)&As[buf][ar][ak] = s;
        #pragma unroll
        for (int u = 0; u < 2; u++) {
            float4 xv = bReg[u];
            xv.x = fmaxf(fmaf(xv.x, bSc, bSh), 0.f);
            xv.y = fmaxf(fmaf(xv.y, bSc, bSh), 0.f);
            xv.z = fmaxf(fmaf(xv.z, bSc, bSh), 0.f);
            xv.w = fmaxf(fmaf(xv.w, bSc, bSh), 0.f);
            uint4 o;
            o.x = f2tf(xv.x); o.y = f2tf(xv.y);
            o.z = f2tf(xv.z); o.w = f2tf(xv.w);
            *(uint4*)&Bs[buf][bk][bn + u * 4] = o;
        }
    };

    int nk = I >> 4;
    load_tile(0);
    store_tile(0);
    __syncthreads();

    for (int kt = 0; kt < nk; kt++) {
        int cur = kt & 1;
        if (kt + 1 < nk) load_tile((kt + 1) << 4);
        #pragma unroll
        for (int ks = 0; ks < 16; ks += 8) {
            uint32_t bfr[4][2];
            #pragma unroll
            for (int nt = 0; nt < 4; nt++) {
                int n = warp_n + nt * 8 + g;
                bfr[nt][0] = Bs[cur][ks + q][n];
                bfr[nt][1] = Bs[cur][ks + q + 4][n];
            }
            #pragma unroll
            for (int mt = 0; mt < 2; mt++) {
                int m = warp_m + mt * 16 + g;
                uint32_t a[4];
                a[0] = As[cur][m][ks + q];
                a[1] = As[cur][m + 8][ks + q];
                a[2] = As[cur][m][ks + q + 4];
                a[3] = As[cur][m + 8][ks + q + 4];
                #pragma unroll
                for (int nt = 0; nt < 4; nt++)
                    mma8(acc[mt][nt], a, bfr[nt]);
            }
        }
        if (kt + 1 < nk) store_tile(cur ^ 1);
        __syncthreads();
    }
}

// Epilogue; STATS=1 additionally accumulates per-channel sum/sumsq into
// g_bnsum/g_bnsq (quad shfl-reduce, then atomicAdd from lane q==0).
template<int STATS>
__device__ __forceinline__ void gemm_epilogue(
    float acc[2][4][4], const float* __restrict__ bias,
    float* __restrict__ Ob, int row0, int col0, int addOut)
{
    int t = threadIdx.x; int lane = t & 31; int w = t >> 5;
    int g = lane >> 2, q = lane & 3;
    int warp_m = (w >> 2) * 32, warp_n = (w & 3) * 32;
    #pragma unroll
    for (int mt = 0; mt < 2; mt++) {
        #pragma unroll
        for (int half = 0; half < 2; half++) {
            int r = row0 + warp_m + mt * 16 + g + half * 8;
            float bb = bias[r];
            float rs = 0.f, rq = 0.f;
            #pragma unroll
            for (int nt = 0; nt < 4; nt++) {
                int c = col0 + warp_n + nt * 8 + 2 * q;
                float* p = &Ob[(size_t)r * NN + c];
                float v0 = acc[mt][nt][half * 2 + 0] + bb;
                float v1 = acc[mt][nt][half * 2 + 1] + bb;
                if (addOut) { float2 e = *(const float2*)p; v0 += e.x; v1 += e.y; }
                float2 o; o.x = v0; o.y = v1;
                *(float2*)p = o;
                if (STATS) { rs += v0 + v1; rq += v0 * v0 + v1 * v1; }
            }
            if (STATS) {
                rs += __shfl_xor_sync(0xffffffffu, rs, 1);
                rs += __shfl_xor_sync(0xffffffffu, rs, 2);
                rq += __shfl_xor_sync(0xffffffffu, rq, 1);
                rq += __shfl_xor_sync(0xffffffffu, rq, 2);
                if (q == 0) {
                    atomicAdd(&g_bnsum[r], rs);
                    atomicAdd(&g_bnsq[r], rq);
                }
            }
        }
    }
}

// Fused Q/K/V projection: logical rows 0-255 = Q, 256-511 = K, 512-767 = V.
// Block (0,0,0) also re-zeroes the BN accumulators for this layer's conv1.
__global__ __launch_bounds__(256, 2) void qkv_mma(
    const float* __restrict__ Wq, const float* __restrict__ bq,
    const float* __restrict__ Wk, const float* __restrict__ bk,
    const float* __restrict__ Wv, const float* __restrict__ bv,
    const float* __restrict__ X, int xorMask,
    float* __restrict__ Qo, float* __restrict__ Ko, float* __restrict__ Vo)
{
    extern __shared__ uint32_t sm[];
    uint32_t (*As)[64][36]  = (uint32_t(*)[64][36])sm;
    uint32_t (*Bs)[32][136] = (uint32_t(*)[32][136])(sm + 3 * 64 * 36);
    int b    = blockIdx.z;
    int row0 = blockIdx.y * 64;
    int col0 = blockIdx.x * 128;
    if (blockIdx.x == 0 && blockIdx.y == 0 && blockIdx.z == 0) {
        int t = threadIdx.x;
        g_bnsum[t] = 0.f; g_bnsum[t + 256] = 0.f;
        g_bnsq[t]  = 0.f; g_bnsq[t + 256]  = 0.f;
    }
    int sel  = row0 >> 8;
    int lrow0 = row0 & 255;
    const float* W; const float* bias; float* Out; int xb;
    if (sel == 0)      { W = Wq; bias = bq; Out = Qo; xb = b; }
    else if (sel == 1) { W = Wk; bias = bk; Out = Ko; xb = b ^ xorMask; }
    else               { W = Wv; bias = bv; Out = Vo; xb = b ^ xorMask; }
    const float* XA = X + (size_t)xb * Dd * NN;
    float acc[2][4][4] = {};
    gemm_core_cpa32<0>(W + (size_t)lrow0 * Dd, Dd, XA, nullptr, col0, As, Bs, acc);
    gemm_epilogue<0>(acc, bias, Out + (size_t)b * Dd * NN, lrow0, col0, 0);
}

// conv1 on [X ; X2] with composite weights; accumulates BN stats.
__global__ __launch_bounds__(256, 2) void conv1_mma(
    const float* __restrict__ W, const float* __restrict__ bias,
    const float* __restrict__ X, const float* __restrict__ X2,
    float* __restrict__ Out)
{
    extern __shared__ uint32_t sm[];
    uint32_t (*As)[64][36]  = (uint32_t(*)[64][36])sm;
    uint32_t (*Bs)[32][136] = (uint32_t(*)[32][136])(sm + 3 * 64 * 36);
    int b    = blockIdx.z;
    int row0 = blockIdx.y * 64;
    int col0 = blockIdx.x * 128;
    const float* XA = X + (size_t)b * 256 * NN;
    const float* XB = X2 + (size_t)b * 256 * NN;
    float acc[2][4][4] = {};
    gemm_core_cpa32<1>(W + (size_t)row0 * D2, D2, XA, XB, col0, As, Bs, acc);
    gemm_epilogue<1>(acc, bias, Out + (size_t)b * D2 * NN, row0, col0, 0);
}

// conv2: recomputes BN scale/shift per block from accumulators, then GEMM
// with fused BN+ReLU on the B path (+residual into Dsc).
__global__ __launch_bounds__(256, 2) void conv_bnrelu(
    const float* __restrict__ W, const float* __restrict__ bias,
    const float* __restrict__ gvec, const float* __restrict__ betav,
    const float* __restrict__ X, float* __restrict__ Out)
{
    __shared__ uint32_t As[2][64][20];
    __shared__ uint32_t Bs[2][16][136];
    __shared__ float sSc[D2], sSh[D2];
    int t = threadIdx.x;
    #pragma unroll
    for (int u = 0; u < 2; u++) {
        int c = t + u * 256;
        float s = g_bnsum[c], sq = g_bnsq[c];
        float mean = s * (1.0f / 4096.0f);
        float var  = sq * (1.0f / 4096.0f) - mean * mean;
        float rstd = rsqrtf(var + 1e-5f);
        float sc = gvec[c] * rstd;
        sSc[c] = sc;
        sSh[c] = betav[c] - mean * sc;
    }
    __syncthreads();
    int b    = blockIdx.z;
    int row0 = blockIdx.y * 64;
    int col0 = blockIdx.x * 128;
    const float* XA = X + (size_t)b * (size_t)D2 * NN;
    float acc[2][4][4] = {};
    gemm_core_bnrelu(W + (size_t)row0 * D2, D2, XA, col0, As, Bs, sSc, sSh, acc);
    gemm_epilogue<0>(acc, bias, Out + (size_t)b * Dd * NN, row0, col0, 1);
}

// ---------------------------------------------------------------------------
// Composite-weight precompute (once per launch).
// ---------------------------------------------------------------------------
__global__ __launch_bounds__(256) void copy_w1a(const float* __restrict__ W1)
{
    size_t i = (size_t)blockIdx.x * 256 + threadIdx.x;   // float4 index
    int l   = (int)(i / (D2 * 64));
    int rem = (int)(i % (D2 * 64));
    int r = rem >> 6, c4 = (rem & 63) * 4;
    *(float4*)&g_W1c[(size_t)l * D2 * D2 + (size_t)r * D2 + c4] =
        *(const float4*)&W1[(size_t)l * D2 * D2 + (size_t)r * D2 + c4];
}

__global__ __launch_bounds__(256) void compose_w1(
    const float* __restrict__ W1, const float* __restrict__ Wm)
{
    __shared__ float Asm[64][17];   // [row][k]
    __shared__ float Bsm[16][68];   // [k][col]
    int l = blockIdx.z;
    int row0 = blockIdx.y * 64;
    int col0 = blockIdx.x * 64;
    const float* W1l = W1 + (size_t)l * D2 * D2;
    const float* Wml = Wm + (size_t)l * Dd * Dd;
    float* Out = g_W1c + (size_t)l * D2 * D2;
    int t = threadIdx.x; int tx = t & 15, ty = t >> 4;
    float acc[4][4] = {};
    for (int k0 = 0; k0 < 256; k0 += 16) {
        int lr = t >> 2, lk = (t & 3) * 4;
        float4 wv = *(const float4*)&W1l[(size_t)(row0 + lr) * D2 + 256 + k0 + lk];
        Asm[lr][lk + 0] = wv.x; Asm[lr][lk + 1] = wv.y;
        Asm[lr][lk + 2] = wv.z; Asm[lr][lk + 3] = wv.w;
        float4 xv = *(const float4*)&Wml[(size_t)(k0 + (t >> 4)) * Dd + col0 + (t & 15) * 4];
        *(float4*)&Bsm[t >> 4][(t & 15) * 4] = xv;
        __syncthreads();
        #pragma unroll
        for (int k = 0; k < 16; k++) {
            float a0 = Asm[ty * 4 + 0][k], a1 = Asm[ty * 4 + 1][k];
            float a2 = Asm[ty * 4 + 2][k], a3 = Asm[ty * 4 + 3][k];
            float4 bv = *(const float4*)&Bsm[k][tx * 4];
            acc[0][0] += a0 * bv.x; acc[0][1] += a0 * bv.y; acc[0][2] += a0 * bv.z; acc[0][3] += a0 * bv.w;
            acc[1][0] += a1 * bv.x; acc[1][1] += a1 * bv.y; acc[1][2] += a1 * bv.z; acc[1][3] += a1 * bv.w;
            acc[2][0] += a2 * bv.x; acc[2][1] += a2 * bv.y; acc[2][2] += a2 * bv.z; acc[2][3] += a2 * bv.w;
            acc[3][0] += a3 * bv.x; acc[3][1] += a3 * bv.y; acc[3][2] += a3 * bv.z; acc[3][3] += a3 * bv.w;
        }
        __syncthreads();
    }
    #pragma unroll
    for (int i = 0; i < 4; i++)
        #pragma unroll
        for (int j = 0; j < 4; j++)
            Out[(size_t)(row0 + ty * 4 + i) * D2 + 256 + col0 + tx * 4 + j] = acc[i][j];
}

__global__ __launch_bounds__(256) void compose_b1(
    const float* __restrict__ W1, const float* __restrict__ bm,
    const float* __restrict__ b1)
{
    int i = blockIdx.x * 256 + threadIdx.x;   // LL*D2
    int l = i >> 9, o = i & 511;
    const float* wrow = W1 + (size_t)l * D2 * D2 + (size_t)o * D2 + 256;
    const float* bml = bm + (size_t)l * Dd;
    float s = b1[(size_t)l * D2 + o];
    for (int c = 0; c < 256; c++) s += wrow[c] * bml[c];
    g_b1c[i] = s;
}

// ---------------------------------------------------------------------------
// Flash attention, tf32 mma, cp.async double-buffered K/V, transposed PV.
// Br=64 x Bc=64, 128 threads (4 warps; warp w owns q-rows [16w,16w+16)).
// Q pre-scaled by 1/8 at smem store (exact).
// ---------------------------------------------------------------------------
__global__ __launch_bounds__(128) void attn_mma(
    const float* __restrict__ Q, const float* __restrict__ K,
    const float* __restrict__ V,
    const float* __restrict__ M0, const float* __restrict__ M1,
    float* __restrict__ Xatt)
{
    extern __shared__ uint32_t smu[];
    uint32_t (*Qs)[68]     = (uint32_t(*)[68])smu;                               // [n][d]
    uint32_t (*Ks)[64][72] = (uint32_t(*)[64][72])(smu + 64 * 68);               // 2x [d][m]
    uint32_t (*Vs)[64][68] = (uint32_t(*)[64][68])(smu + 64 * 68 + 2 * 64 * 72); // 2x [d][m]
    uint32_t (*Ps)[72]     = (uint32_t(*)[72])(smu + 64 * 68 + 2 * 64 * 72 + 2 * 64 * 68); // [m][n]
    float    (*Osf)[72]    = (float(*)[72])Ps;

    int bh = blockIdx.y; int b = bh >> 2, h = bh & 3;
    int n0 = blockIdx.x * 64;
    int t = threadIdx.x;
    int lane = t & 31, w = t >> 5;
    int g = lane >> 2, q = lane & 3;
    int rowb = w * 16;

    const float* Qb = Q + (size_t)b * Dd * NN;
    const float* Kb = K + (size_t)b * Dd * NN;
    const float* Vb = V + (size_t)b * Dd * NN;
    const float* Mb = (b < 2) ? M0 + (size_t)b * NN * NN
                              : M1 + (size_t)(b - 2) * NN * NN;

    // Q tile transpose-load -> Qs[n][d], pre-scaled by 1/8 (exact)
    {
        int d = t >> 1, nc = (t & 1) * 32;
        const float* gp = &Qb[(size_t)(d * 4 + h) * NN + n0 + nc];
        #pragma unroll
        for (int u = 0; u < 8; u++) {
            float4 v = *(const float4*)(gp + u * 4);
            Qs[nc + u * 4 + 0][d] = __float_as_uint(v.x * 0.125f);
            Qs[nc + u * 4 + 1][d] = __float_as_uint(v.y * 0.125f);
            Qs[nc + u * 4 + 2][d] = __float_as_uint(v.z * 0.125f);
            Qs[nc + u * 4 + 3][d] = __float_as_uint(v.w * 0.125f);
        }
    }

    auto issue_kv = [&](int it) {
        int buf = it & 1, mt = it << 6;
        #pragma unroll
        for (int u = 0; u < 8; u++) {
            int cr = u * 8 + (t >> 4);
            int cc = (t & 15) * 4;
            cp16(&Ks[buf][cr][cc], &Kb[(size_t)(cr * 4 + h) * NN + mt + cc]);
            cp16(&Vs[buf][cr][cc], &Vb[(size_t)(cr * 4 + h) * NN + mt + cc]);
        }
        asm volatile("cp.async.commit_group;" ::: "memory");
    };

    float oacc[4][2][4] = {};
    float m0r = -1e30f, m1r = -1e30f, l0 = 0.f, l1 = 0.f;
    int r0g = n0 + rowb + g, r1g = r0g + 8;

    issue_kv(0);

    for (int it = 0; it < 16; it++) {
        int buf = it & 1, mt = it << 6;
        asm volatile("cp.async.wait_group 0;" ::: "memory");
        __syncthreads();
        if (it + 1 < 16) issue_kv(it + 1);

        float sacc[8][4] = {};
        #pragma unroll
        for (int ks = 0; ks < 8; ks++) {
            int kk = ks * 8;
            uint32_t a[4];
            a[0] = Qs[rowb + g][kk + q];
            a[1] = Qs[rowb + g + 8][kk + q];
            a[2] = Qs[rowb + g][kk + q + 4];
            a[3] = Qs[rowb + g + 8][kk + q + 4];
            #pragma unroll
            for (int nf = 0; nf < 8; nf++) {
                uint32_t bb[2];
                bb[0] = Ks[buf][kk + q][nf * 8 + g];
                bb[1] = Ks[buf][kk + q + 4][nf * 8 + g];
                mma8(sacc[nf], a, bb);
            }
        }

        const float* mr0 = Mb + (size_t)r0g * NN + mt;
        const float* mr1 = Mb + (size_t)r1g * NN + mt;
        float v0[16], v1[16];
        float rm0 = -1e30f, rm1 = -1e30f;
        #pragma unroll
        for (int nf = 0; nf < 8; nf++) {
            int c = nf * 8 + 2 * q;
            float2 k0v = *(const float2*)&mr0[c];
            float2 k1v = *(const float2*)&mr1[c];
            v0[2 * nf]     = sacc[nf][0] * k0v.x;
            v0[2 * nf + 1] = sacc[nf][1] * k0v.y;
            v1[2 * nf]     = sacc[nf][2] * k1v.x;
            v1[2 * nf + 1] = sacc[nf][3] * k1v.y;
            rm0 = fmaxf(rm0, fmaxf(v0[2 * nf], v0[2 * nf + 1]));
            rm1 = fmaxf(rm1, fmaxf(v1[2 * nf], v1[2 * nf + 1]));
        }
        rm0 = fmaxf(rm0, __shfl_xor_sync(0xffffffffu, rm0, 1));
        rm0 = fmaxf(rm0, __shfl_xor_sync(0xffffffffu, rm0, 2));
        rm1 = fmaxf(rm1, __shfl_xor_sync(0xffffffffu, rm1, 1));
        rm1 = fmaxf(rm1, __shfl_xor_sync(0xffffffffu, rm1, 2));
        float nm0 = fmaxf(m0r, rm0), nm1 = fmaxf(m1r, rm1);
        float rs0 = 0.f, rs1 = 0.f;
        #pragma unroll
        for (int i = 0; i < 16; i++) {
            v0[i] = __expf(v0[i] - nm0); rs0 += v0[i];
            v1[i] = __expf(v1[i] - nm1); rs1 += v1[i];
        }
        rs0 += __shfl_xor_sync(0xffffffffu, rs0, 1);
        rs0 += __shfl_xor_sync(0xffffffffu, rs0, 2);
        rs1 += __shfl_xor_sync(0xffffffffu, rs1, 1);
        rs1 += __shfl_xor_sync(0xffffffffu, rs1, 2);
        float f0 = __expf(m0r - nm0), f1 = __expf(m1r - nm1);
        m0r = nm0; m1r = nm1;
        l0 = l0 * f0 + rs0;
        l1 = l1 * f1 + rs1;

        {
            float fA = __shfl_sync(0xffffffffu, f0, 8 * q);
            float fB = __shfl_sync(0xffffffffu, f0, 8 * q + 4);
            float fC = __shfl_sync(0xffffffffu, f1, 8 * q);
            float fD = __shfl_sync(0xffffffffu, f1, 8 * q + 4);
            #pragma unroll
            for (int df = 0; df < 4; df++) {
                oacc[df][0][0] *= fA; oacc[df][0][1] *= fB;
                oacc[df][0][2] *= fA; oacc[df][0][3] *= fB;
                oacc[df][1][0] *= fC; oacc[df][1][1] *= fD;
                oacc[df][1][2] *= fC; oacc[df][1][3] *= fD;
            }
        }

        #pragma unroll
        for (int nf = 0; nf < 8; nf++) {
            Ps[nf * 8 + 2 * q][rowb + g]         = __float_as_uint(v0[2 * nf]);
            Ps[nf * 8 + 2 * q + 1][rowb + g]     = __float_as_uint(v0[2 * nf + 1]);
            Ps[nf * 8 + 2 * q][rowb + g + 8]     = __float_as_uint(v1[2 * nf]);
            Ps[nf * 8 + 2 * q + 1][rowb + g + 8] = __float_as_uint(v1[2 * nf + 1]);
        }
        __syncwarp();

        #pragma unroll
        for (int ks = 0; ks < 8; ks++) {
            int kk = ks * 8;
            uint32_t bb0[2], bb1[2];
            bb0[0] = Ps[kk + q][rowb + g];
            bb0[1] = Ps[kk + q + 4][rowb + g];
            bb1[0] = Ps[kk + q][rowb + 8 + g];
            bb1[1] = Ps[kk + q + 4][rowb + 8 + g];
            #pragma unroll
            for (int df = 0; df < 4; df++) {
                uint32_t a[4];
                a[0] = Vs[buf][df * 16 + g][kk + q];
                a[1] = Vs[buf][df * 16 + 8 + g][kk + q];
                a[2] = Vs[buf][df * 16 + g][kk + q + 4];
                a[3] = Vs[buf][df * 16 + 8 + g][kk + q + 4];
                mma8(oacc[df][0], a, bb0);
                mma8(oacc[df][1], a, bb1);
            }
        }
        __syncwarp();
    }

    float invA = 1.0f / __shfl_sync(0xffffffffu, l0, 8 * q);
    float invB = 1.0f / __shfl_sync(0xffffffffu, l0, 8 * q + 4);
    float invC = 1.0f / __shfl_sync(0xffffffffu, l1, 8 * q);
    float invD = 1.0f / __shfl_sync(0xffffffffu, l1, 8 * q + 4);
    __syncthreads();
    #pragma unroll
    for (int df = 0; df < 4; df++) {
        int d0 = df * 16 + g, d1 = d0 + 8;
        float2 p;
        p.x = oacc[df][0][0] * invA; p.y = oacc[df][0][1] * invB;
        *(float2*)&Osf[d0][rowb + 2 * q] = p;
        p.x = oacc[df][0][2] * invA; p.y = oacc[df][0][3] * invB;
        *(float2*)&Osf[d1][rowb + 2 * q] = p;
        p.x = oacc[df][1][0] * invC; p.y = oacc[df][1][1] * invD;
        *(float2*)&Osf[d0][rowb + 8 + 2 * q] = p;
        p.x = oacc[df][1][2] * invC; p.y = oacc[df][1][3] * invD;
        *(float2*)&Osf[d1][rowb + 8 + 2 * q] = p;
    }
    __syncthreads();
    {
        int d = t >> 1, nc = (t & 1) * 32;
        float* op = &Xatt[(size_t)b * Dd * NN + (size_t)(d * 4 + h) * NN + n0 + nc];
        #pragma unroll
        for (int u = 0; u < 8; u++)
            *(float4*)(op + u * 4) = *(const float4*)&Osf[d][nc + u * 4];
    }
}

// ---------------------------------------------------------------------------
extern "C" void kernel_launch(void* const* d_in, const int* in_sizes, int n_in,
                              void* d_out, int out_size)
{
    const float* desc0 = (const float*)d_in[0];
    const float* desc1 = (const float*)d_in[1];
    const float* M0    = (const float*)d_in[2];
    const float* M1    = (const float*)d_in[3];
    const float* Wq = (const float*)d_in[4];
    const float* bq = (const float*)d_in[5];
    const float* Wk = (const float*)d_in[6];
    const float* bk = (const float*)d_in[7];
    const float* Wv = (const float*)d_in[8];
    const float* bv = (const float*)d_in[9];
    const float* Wm = (const float*)d_in[10];
    const float* bm = (const float*)d_in[11];
    const float* W1 = (const float*)d_in[12];
    const float* b1 = (const float*)d_in[13];
    const float* g1 = (const float*)d_in[14];
    const float* be1 = (const float*)d_in[15];
    const float* W2 = (const float*)d_in[16];
    const float* b2 = (const float*)d_in[17];

    float* Dsc = (float*)d_out;   // [4, 256, 1024] — doubles as the output

    float *Q, *K, *V, *Xatt, *Y1, *W1c, *b1c;
    cudaGetSymbolAddress((void**)&Q,    g_Q);
    cudaGetSymbolAddress((void**)&K,    g_K);
    cudaGetSymbolAddress((void**)&V,    g_V);
    cudaGetSymbolAddress((void**)&Xatt, g_Xatt);
    cudaGetSymbolAddress((void**)&Y1,   g_Y1);
    cudaGetSymbolAddress((void**)&W1c,  g_W1c);
    cudaGetSymbolAddress((void**)&b1c,  g_b1c);

    static const int ATTN_SMEM = (64 * 68 + 2 * 64 * 72 + 2 * 64 * 68 + 64 * 72) * 4; // 107520
    static const int CPA_SMEM  = (3 * 64 * 36 + 3 * 32 * 136) * 4;                    // 79872
    cudaFuncSetAttribute(attn_mma,  cudaFuncAttributeMaxDynamicSharedMemorySize, ATTN_SMEM);
    cudaFuncSetAttribute(qkv_mma,   cudaFuncAttributeMaxDynamicSharedMemorySize, CPA_SMEM);
    cudaFuncSetAttribute(conv1_mma, cudaFuncAttributeMaxDynamicSharedMemorySize, CPA_SMEM);

    size_t descBytes = (size_t)2 * Dd * NN * sizeof(float);
    cudaMemcpyAsync(Dsc,               desc0, descBytes, cudaMemcpyDeviceToDevice, 0);
    cudaMemcpyAsync(Dsc + 2 * Dd * NN, desc1, descBytes, cudaMemcpyDeviceToDevice, 0);

    // One-shot composite-weight precompute (merge GEMM folded into conv1)
    copy_w1a<<<768, 256>>>(W1);
    compose_w1<<<dim3(4, 8, LL), 256>>>(W1, Wm);
    compose_b1<<<(LL * D2) / 256, 256>>>(W1, bm, b1);

    static const int crossFlag[LL] = {0, 1, 0, 1, 0, 1};

    for (int i = 0; i < LL; i++) {
        int xm = crossFlag[i] ? 2 : 0;
        const float* Wqi = Wq + (size_t)i * Dd * Dd;
        const float* bqi = bq + (size_t)i * Dd;
        const float* Wki = Wk + (size_t)i * Dd * Dd;
        const float* bki = bk + (size_t)i * Dd;
        const float* Wvi = Wv + (size_t)i * Dd * Dd;
        const float* bvi = bv + (size_t)i * Dd;
        const float* g1i = g1 + (size_t)i * D2;
        const float* be1i = be1 + (size_t)i * D2;
        const float* W2i = W2 + (size_t)i * Dd * D2;
        const float* b2i = b2 + (size_t)i * Dd;

        // Fused Q/K/V projections; block 0 zeroes BN accumulators for conv1
        qkv_mma<<<dim3(8, 12, 4), 256, CPA_SMEM>>>(Wqi, bqi, Wki, bki, Wvi, bvi,
                                                   Dsc, xm, Q, K, V);

        attn_mma<<<dim3(16, 16), 128, ATTN_SMEM>>>(Q, K, V, M0, M1, Xatt);

        // conv1 with composite weights on [Dsc ; Xatt]; BN stats fused in epilogue
        conv1_mma<<<dim3(8, 8, 4), 256, CPA_SMEM>>>(W1c + (size_t)i * D2 * D2,
                                                    b1c + (size_t)i * D2,
                                                    Dsc, Xatt, Y1);

        // conv2: per-block BN finalize (from accumulators) + BN+ReLU + residual
        conv_bnrelu<<<dim3(8, 4, 4), 256>>>(W2i, b2i, g1i, be1i, Y1, Dsc);
    }
}

// round 16
// speedup vs baseline: 1.0624x; 1.0169x over previous
#include <cuda_runtime.h>
#include <cstdint>

#define B4   4      // 2*BS concatenated batch
#define Dd   256    // feature dim
#define D2   512
#define NN   1024   // keypoints
#define LL   6

// Scratch (device globals; no allocation allowed)
__device__ float g_Q[B4 * Dd * NN];
__device__ float g_K[B4 * Dd * NN];
__device__ float g_V[B4 * Dd * NN];
__device__ float g_Xatt[B4 * Dd * NN];
__device__ float g_Y1[B4 * D2 * NN];
__device__ float g_bnsum[D2];
__device__ float g_bnsq[D2];
__device__ float g_W1c[LL * D2 * D2];   // composite [W1a | W1b@Wm] per layer
__device__ float g_b1c[LL * D2];        // composite b1 + W1b@bm

__device__ __forceinline__ uint32_t f2tf(float f) {
    uint32_t u; asm("cvt.rna.tf32.f32 %0, %1;" : "=r"(u) : "f"(f)); return u;
}
__device__ __forceinline__ void mma8(float c[4], const uint32_t a[4], const uint32_t b[2]) {
    asm volatile("mma.sync.aligned.m16n8k8.row.col.f32.tf32.tf32.f32 "
        "{%0,%1,%2,%3}, {%4,%5,%6,%7}, {%8,%9}, {%0,%1,%2,%3};"
        : "+f"(c[0]), "+f"(c[1]), "+f"(c[2]), "+f"(c[3])
        : "r"(a[0]), "r"(a[1]), "r"(a[2]), "r"(a[3]), "r"(b[0]), "r"(b[1]));
}
__device__ __forceinline__ void cp16(void* dst, const void* src) {
    uint32_t d = (uint32_t)__cvta_generic_to_shared(dst);
    asm volatile("cp.async.ca.shared.global [%0], [%1], 16;" :: "r"(d), "l"(src));
}

// ---------------------------------------------------------------------------
// cp.async 3-stage pipelined tf32 GEMM core, BK=32. Block 64(M) x 128(N),
// 256 threads (8 warps, 32x32 warp tile). A smem [m][k] stride 36 (frag bank
// 4g conflict-free), B smem [k][n] stride 136 (frag bank 8q+g conflict-free).
// ---------------------------------------------------------------------------
template<int CONCAT>
__device__ __forceinline__ void gemm_core_cpa32(
    const float* __restrict__ Wp, int I,
    const float* __restrict__ XA, const float* __restrict__ XB,
    int col0, uint32_t (*As)[64][36], uint32_t (*Bs)[32][136],
    float acc[2][4][4])
{
    int t = threadIdx.x;
    int lane = t & 31, w = t >> 5;
    int g = lane >> 2, q = lane & 3;
    int warp_m = (w >> 2) * 32, warp_n = (w & 3) * 32;
    int ar = t >> 2, ak = (t & 3) * 8;   // A: 2x16B per thread
    int bk = t >> 4, bn = (t & 15) * 8;  // B: 4x16B per thread (k and k+16)

    auto issue = [&](int kt) {
        int buf = kt % 3;
        int k0 = kt << 5;
        const float* wr = &Wp[(size_t)ar * I + k0 + ak];
        cp16(&As[buf][ar][ak],     wr);
        cp16(&As[buf][ar][ak + 4], wr + 4);
        #pragma unroll
        for (int half = 0; half < 2; half++) {
            int ch = k0 + bk + half * 16;
            const float* src = XA; int chl = ch;
            if (CONCAT && ch >= 256) { src = XB; chl = ch - 256; }
            const float* gp = &src[(size_t)chl * NN + col0 + bn];
            cp16(&Bs[buf][bk + half * 16][bn],     gp);
            cp16(&Bs[buf][bk + half * 16][bn + 4], gp + 4);
        }
        asm volatile("cp.async.commit_group;" ::: "memory");
    };

    int nk = I >> 5;
    issue(0);
    if (nk > 1) issue(1);

    for (int kt = 0; kt < nk; kt++) {
        if (kt + 1 < nk) asm volatile("cp.async.wait_group 1;" ::: "memory");
        else             asm volatile("cp.async.wait_group 0;" ::: "memory");
        __syncthreads();
        int cur = kt % 3;
        #pragma unroll
        for (int ks = 0; ks < 32; ks += 8) {
            uint32_t bfr[4][2];
            #pragma unroll
            for (int nt = 0; nt < 4; nt++) {
                int n = warp_n + nt * 8 + g;
                bfr[nt][0] = Bs[cur][ks + q][n];
                bfr[nt][1] = Bs[cur][ks + q + 4][n];
            }
            #pragma unroll
            for (int mt = 0; mt < 2; mt++) {
                int m = warp_m + mt * 16 + g;
                uint32_t a[4];
                a[0] = As[cur][m][ks + q];
                a[1] = As[cur][m + 8][ks + q];
                a[2] = As[cur][m][ks + q + 4];
                a[3] = As[cur][m + 8][ks + q + 4];
                #pragma unroll
                for (int nt = 0; nt < 4; nt++)
                    mma8(acc[mt][nt], a, bfr[nt]);
            }
        }
        // issue(kt+2) writes buf (kt-1)%3, consumed at iter kt-1 (done before
        // this iteration's barrier) -> safe.
        if (kt + 2 < nk) issue(kt + 2);
    }
}

// Register-staged double-buffered BK=32 core with BN+ReLU transform on the
// B-load path; scale/shift come from a block-local smem table. 16 barriers
// for the 512-deep conv2 GEMM (vs 32 at BK=16).
__device__ __forceinline__ void gemm_core_bnrelu32(
    const float* __restrict__ Wp, int I,
    const float* __restrict__ XA,
    int col0, uint32_t (*As)[64][36], uint32_t (*Bs)[32][136],
    const float* __restrict__ sSc, const float* __restrict__ sSh,
    float acc[2][4][4])
{
    int t = threadIdx.x;
    int lane = t & 31, w = t >> 5;
    int g = lane >> 2, q = lane & 3;
    int warp_m = (w >> 2) * 32, warp_n = (w & 3) * 32;
    int ar = t >> 2, ak = (t & 3) * 8;   // A: rows 0..63, 8-col chunk
    int bk = t >> 4, bn = (t & 15) * 8;  // B: k rows bk and bk+16

    float4 aReg[2];
    float4 bReg[2][2];
    float bSc[2], bSh[2];

    auto load_tile = [&](int k0) {
        aReg[0] = *(const float4*)&Wp[(size_t)ar * I + k0 + ak];
        aReg[1] = *(const float4*)&Wp[(size_t)ar * I + k0 + ak + 4];
        #pragma unroll
        for (int half = 0; half < 2; half++) {
            int ch = k0 + bk + half * 16;
            const float* gp = &XA[(size_t)ch * NN + col0 + bn];
            bSc[half] = sSc[ch]; bSh[half] = sSh[ch];
            bReg[half][0] = *(const float4*)gp;
            bReg[half][1] = *(const float4*)(gp + 4);
        }
    };
    auto store_tile = [&](int buf) {
        #pragma unroll
        for (int u = 0; u < 2; u++) {
            uint4 s;
            s.x = f2tf(aReg[u].x); s.y = f2tf(aReg[u].y);
            s.z = f2tf(aReg[u].z); s.w = f2tf(aReg[u].w);
            *(uint4*)&As[buf][ar][ak + u * 4] = s;
        }
        #pragma unroll
        for (int half = 0; half < 2; half++) {
            #pragma unroll
            for (int u = 0; u < 2; u++) {
                float4 xv = bReg[half][u];
                xv.x = fmaxf(fmaf(xv.x, bSc[half], bSh[half]), 0.f);
                xv.y = fmaxf(fmaf(xv.y, bSc[half], bSh[half]), 0.f);
                xv.z = fmaxf(fmaf(xv.z, bSc[half], bSh[half]), 0.f);
                xv.w = fmaxf(fmaf(xv.w, bSc[half], bSh[half]), 0.f);
                uint4 o;
                o.x = f2tf(xv.x); o.y = f2tf(xv.y);
                o.z = f2tf(xv.z); o.w = f2tf(xv.w);
                *(uint4*)&Bs[buf][bk + half * 16][bn + u * 4] = o;
            }
        }
    };

    int nk = I >> 5;
    load_tile(0);
    store_tile(0);
    __syncthreads();

    for (int kt = 0; kt < nk; kt++) {
        int cur = kt & 1;
        if (kt + 1 < nk) load_tile((kt + 1) << 5);
        #pragma unroll
        for (int ks = 0; ks < 32; ks += 8) {
            uint32_t bfr[4][2];
            #pragma unroll
            for (int nt = 0; nt < 4; nt++) {
                int n = warp_n + nt * 8 + g;
                bfr[nt][0] = Bs[cur][ks + q][n];
                bfr[nt][1] = Bs[cur][ks + q + 4][n];
            }
            #pragma unroll
            for (int mt = 0; mt < 2; mt++) {
                int m = warp_m + mt * 16 + g;
                uint32_t a[4];
                a[0] = As[cur][m][ks + q];
                a[1] = As[cur][m + 8][ks + q];
                a[2] = As[cur][m][ks + q + 4];
                a[3] = As[cur][m + 8][ks + q + 4];
                #pragma unroll
                for (int nt = 0; nt < 4; nt++)
                    mma8(acc[mt][nt], a, bfr[nt]);
            }
        }
        if (kt + 1 < nk) store_tile(cur ^ 1);
        __syncthreads();
    }
}

// Epilogue; STATS=1 additionally accumulates per-channel sum/sumsq into
// g_bnsum/g_bnsq (quad shfl-reduce, then atomicAdd from lane q==0).
template<int STATS>
__device__ __forceinline__ void gemm_epilogue(
    float acc[2][4][4], const float* __restrict__ bias,
    float* __restrict__ Ob, int row0, int col0, int addOut)
{
    int t = threadIdx.x; int lane = t & 31; int w = t >> 5;
    int g = lane >> 2, q = lane & 3;
    int warp_m = (w >> 2) * 32, warp_n = (w & 3) * 32;
    #pragma unroll
    for (int mt = 0; mt < 2; mt++) {
        #pragma unroll
        for (int half = 0; half < 2; half++) {
            int r = row0 + warp_m + mt * 16 + g + half * 8;
            float bb = bias[r];
            float rs = 0.f, rq = 0.f;
            #pragma unroll
            for (int nt = 0; nt < 4; nt++) {
                int c = col0 + warp_n + nt * 8 + 2 * q;
                float* p = &Ob[(size_t)r * NN + c];
                float v0 = acc[mt][nt][half * 2 + 0] + bb;
                float v1 = acc[mt][nt][half * 2 + 1] + bb;
                if (addOut) { float2 e = *(const float2*)p; v0 += e.x; v1 += e.y; }
                float2 o; o.x = v0; o.y = v1;
                *(float2*)p = o;
                if (STATS) { rs += v0 + v1; rq += v0 * v0 + v1 * v1; }
            }
            if (STATS) {
                rs += __shfl_xor_sync(0xffffffffu, rs, 1);
                rs += __shfl_xor_sync(0xffffffffu, rs, 2);
                rq += __shfl_xor_sync(0xffffffffu, rq, 1);
                rq += __shfl_xor_sync(0xffffffffu, rq, 2);
                if (q == 0) {
                    atomicAdd(&g_bnsum[r], rs);
                    atomicAdd(&g_bnsq[r], rq);
                }
            }
        }
    }
}

// Fused Q/K/V projection: logical rows 0-255 = Q, 256-511 = K, 512-767 = V.
// Block (0,0,0) also re-zeroes the BN accumulators for this layer's conv1.
__global__ __launch_bounds__(256, 2) void qkv_mma(
    const float* __restrict__ Wq, const float* __restrict__ bq,
    const float* __restrict__ Wk, const float* __restrict__ bk,
    const float* __restrict__ Wv, const float* __restrict__ bv,
    const float* __restrict__ X, int xorMask,
    float* __restrict__ Qo, float* __restrict__ Ko, float* __restrict__ Vo)
{
    extern __shared__ uint32_t sm[];
    uint32_t (*As)[64][36]  = (uint32_t(*)[64][36])sm;
    uint32_t (*Bs)[32][136] = (uint32_t(*)[32][136])(sm + 3 * 64 * 36);
    int b    = blockIdx.z;
    int row0 = blockIdx.y * 64;
    int col0 = blockIdx.x * 128;
    if (blockIdx.x == 0 && blockIdx.y == 0 && blockIdx.z == 0) {
        int t = threadIdx.x;
        g_bnsum[t] = 0.f; g_bnsum[t + 256] = 0.f;
        g_bnsq[t]  = 0.f; g_bnsq[t + 256]  = 0.f;
    }
    int sel  = row0 >> 8;
    int lrow0 = row0 & 255;
    const float* W; const float* bias; float* Out; int xb;
    if (sel == 0)      { W = Wq; bias = bq; Out = Qo; xb = b; }
    else if (sel == 1) { W = Wk; bias = bk; Out = Ko; xb = b ^ xorMask; }
    else               { W = Wv; bias = bv; Out = Vo; xb = b ^ xorMask; }
    const float* XA = X + (size_t)xb * Dd * NN;
    float acc[2][4][4] = {};
    gemm_core_cpa32<0>(W + (size_t)lrow0 * Dd, Dd, XA, nullptr, col0, As, Bs, acc);
    gemm_epilogue<0>(acc, bias, Out + (size_t)b * Dd * NN, lrow0, col0, 0);
}

// conv1 on [X ; X2] with composite weights; accumulates BN stats.
__global__ __launch_bounds__(256, 2) void conv1_mma(
    const float* __restrict__ W, const float* __restrict__ bias,
    const float* __restrict__ X, const float* __restrict__ X2,
    float* __restrict__ Out)
{
    extern __shared__ uint32_t sm[];
    uint32_t (*As)[64][36]  = (uint32_t(*)[64][36])sm;
    uint32_t (*Bs)[32][136] = (uint32_t(*)[32][136])(sm + 3 * 64 * 36);
    int b    = blockIdx.z;
    int row0 = blockIdx.y * 64;
    int col0 = blockIdx.x * 128;
    const float* XA = X + (size_t)b * 256 * NN;
    const float* XB = X2 + (size_t)b * 256 * NN;
    float acc[2][4][4] = {};
    gemm_core_cpa32<1>(W + (size_t)row0 * D2, D2, XA, XB, col0, As, Bs, acc);
    gemm_epilogue<1>(acc, bias, Out + (size_t)b * D2 * NN, row0, col0, 0);
}

// conv2: recomputes BN scale/shift per block from accumulators, then GEMM
// with fused BN+ReLU on the B path (+residual into Dsc). BK=32.
__global__ __launch_bounds__(256, 2) void conv_bnrelu(
    const float* __restrict__ W, const float* __restrict__ bias,
    const float* __restrict__ gvec, const float* __restrict__ betav,
    const float* __restrict__ X, float* __restrict__ Out)
{
    __shared__ uint32_t As[2][64][36];
    __shared__ uint32_t Bs[2][32][136];
    __shared__ float sSc[D2], sSh[D2];
    int t = threadIdx.x;
    #pragma unroll
    for (int u = 0; u < 2; u++) {
        int c = t + u * 256;
        float s = g_bnsum[c], sq = g_bnsq[c];
        float mean = s * (1.0f / 4096.0f);
        float var  = sq * (1.0f / 4096.0f) - mean * mean;
        float rstd = rsqrtf(var + 1e-5f);
        float sc = gvec[c] * rstd;
        sSc[c] = sc;
        sSh[c] = betav[c] - mean * sc;
    }
    __syncthreads();
    int b    = blockIdx.z;
    int row0 = blockIdx.y * 64;
    int col0 = blockIdx.x * 128;
    const float* XA = X + (size_t)b * (size_t)D2 * NN;
    float acc[2][4][4] = {};
    gemm_core_bnrelu32(W + (size_t)row0 * D2, D2, XA, col0, As, Bs, sSc, sSh, acc);
    gemm_epilogue<0>(acc, bias, Out + (size_t)b * Dd * NN, row0, col0, 1);
}

// ---------------------------------------------------------------------------
// Composite-weight precompute (once per launch).
// ---------------------------------------------------------------------------
__global__ __launch_bounds__(256) void copy_w1a(const float* __restrict__ W1)
{
    size_t i = (size_t)blockIdx.x * 256 + threadIdx.x;   // float4 index
    int l   = (int)(i / (D2 * 64));
    int rem = (int)(i % (D2 * 64));
    int r = rem >> 6, c4 = (rem & 63) * 4;
    *(float4*)&g_W1c[(size_t)l * D2 * D2 + (size_t)r * D2 + c4] =
        *(const float4*)&W1[(size_t)l * D2 * D2 + (size_t)r * D2 + c4];
}

__global__ __launch_bounds__(256) void compose_w1(
    const float* __restrict__ W1, const float* __restrict__ Wm)
{
    __shared__ float Asm[64][17];   // [row][k]
    __shared__ float Bsm[16][68];   // [k][col]
    int l = blockIdx.z;
    int row0 = blockIdx.y * 64;
    int col0 = blockIdx.x * 64;
    const float* W1l = W1 + (size_t)l * D2 * D2;
    const float* Wml = Wm + (size_t)l * Dd * Dd;
    float* Out = g_W1c + (size_t)l * D2 * D2;
    int t = threadIdx.x; int tx = t & 15, ty = t >> 4;
    float acc[4][4] = {};
    for (int k0 = 0; k0 < 256; k0 += 16) {
        int lr = t >> 2, lk = (t & 3) * 4;
        float4 wv = *(const float4*)&W1l[(size_t)(row0 + lr) * D2 + 256 + k0 + lk];
        Asm[lr][lk + 0] = wv.x; Asm[lr][lk + 1] = wv.y;
        Asm[lr][lk + 2] = wv.z; Asm[lr][lk + 3] = wv.w;
        float4 xv = *(const float4*)&Wml[(size_t)(k0 + (t >> 4)) * Dd + col0 + (t & 15) * 4];
        *(float4*)&Bsm[t >> 4][(t & 15) * 4] = xv;
        __syncthreads();
        #pragma unroll
        for (int k = 0; k < 16; k++) {
            float a0 = Asm[ty * 4 + 0][k], a1 = Asm[ty * 4 + 1][k];
            float a2 = Asm[ty * 4 + 2][k], a3 = Asm[ty * 4 + 3][k];
            float4 bv = *(const float4*)&Bsm[k][tx * 4];
            acc[0][0] += a0 * bv.x; acc[0][1] += a0 * bv.y; acc[0][2] += a0 * bv.z; acc[0][3] += a0 * bv.w;
            acc[1][0] += a1 * bv.x; acc[1][1] += a1 * bv.y; acc[1][2] += a1 * bv.z; acc[1][3] += a1 * bv.w;
            acc[2][0] += a2 * bv.x; acc[2][1] += a2 * bv.y; acc[2][2] += a2 * bv.z; acc[2][3] += a2 * bv.w;
            acc[3][0] += a3 * bv.x; acc[3][1] += a3 * bv.y; acc[3][2] += a3 * bv.z; acc[3][3] += a3 * bv.w;
        }
        __syncthreads();
    }
    #pragma unroll
    for (int i = 0; i < 4; i++)
        #pragma unroll
        for (int j = 0; j < 4; j++)
            Out[(size_t)(row0 + ty * 4 + i) * D2 + 256 + col0 + tx * 4 + j] = acc[i][j];
}

__global__ __launch_bounds__(256) void compose_b1(
    const float* __restrict__ W1, const float* __restrict__ bm,
    const float* __restrict__ b1)
{
    int i = blockIdx.x * 256 + threadIdx.x;   // LL*D2
    int l = i >> 9, o = i & 511;
    const float* wrow = W1 + (size_t)l * D2 * D2 + (size_t)o * D2 + 256;
    const float* bml = bm + (size_t)l * Dd;
    float s = b1[(size_t)l * D2 + o];
    for (int c = 0; c < 256; c++) s += wrow[c] * bml[c];
    g_b1c[i] = s;
}

// ---------------------------------------------------------------------------
// Flash attention, tf32 mma, cp.async double-buffered K/V, transposed PV.
// Br=64 x Bc=64, 128 threads (4 warps; warp w owns q-rows [16w,16w+16)).
// (exact R11 version: 0.125 applied at the mask stage)
// ---------------------------------------------------------------------------
__global__ __launch_bounds__(128) void attn_mma(
    const float* __restrict__ Q, const float* __restrict__ K,
    const float* __restrict__ V,
    const float* __restrict__ M0, const float* __restrict__ M1,
    float* __restrict__ Xatt)
{
    extern __shared__ uint32_t smu[];
    uint32_t (*Qs)[68]     = (uint32_t(*)[68])smu;                               // [n][d]
    uint32_t (*Ks)[64][72] = (uint32_t(*)[64][72])(smu + 64 * 68);               // 2x [d][m]
    uint32_t (*Vs)[64][68] = (uint32_t(*)[64][68])(smu + 64 * 68 + 2 * 64 * 72); // 2x [d][m]
    uint32_t (*Ps)[72]     = (uint32_t(*)[72])(smu + 64 * 68 + 2 * 64 * 72 + 2 * 64 * 68); // [m][n]
    float    (*Osf)[72]    = (float(*)[72])Ps;

    int bh = blockIdx.y; int b = bh >> 2, h = bh & 3;
    int n0 = blockIdx.x * 64;
    int t = threadIdx.x;
    int lane = t & 31, w = t >> 5;
    int g = lane >> 2, q = lane & 3;
    int rowb = w * 16;

    const float* Qb = Q + (size_t)b * Dd * NN;
    const float* Kb = K + (size_t)b * Dd * NN;
    const float* Vb = V + (size_t)b * Dd * NN;
    const float* Mb = (b < 2) ? M0 + (size_t)b * NN * NN
                              : M1 + (size_t)(b - 2) * NN * NN;

    {
        int d = t >> 1, nc = (t & 1) * 32;
        const float* gp = &Qb[(size_t)(d * 4 + h) * NN + n0 + nc];
        #pragma unroll
        for (int u = 0; u < 8; u++) {
            float4 v = *(const float4*)(gp + u * 4);
            Qs[nc + u * 4 + 0][d] = __float_as_uint(v.x);
            Qs[nc + u * 4 + 1][d] = __float_as_uint(v.y);
            Qs[nc + u * 4 + 2][d] = __float_as_uint(v.z);
            Qs[nc + u * 4 + 3][d] = __float_as_uint(v.w);
        }
    }

    auto issue_kv = [&](int it) {
        int buf = it & 1, mt = it << 6;
        #pragma unroll
        for (int u = 0; u < 8; u++) {
            int cr = u * 8 + (t >> 4);
            int cc = (t & 15) * 4;
            cp16(&Ks[buf][cr][cc], &Kb[(size_t)(cr * 4 + h) * NN + mt + cc]);
            cp16(&Vs[buf][cr][cc], &Vb[(size_t)(cr * 4 + h) * NN + mt + cc]);
        }
        asm volatile("cp.async.commit_group;" ::: "memory");
    };

    float oacc[4][2][4] = {};
    float m0r = -1e30f, m1r = -1e30f, l0 = 0.f, l1 = 0.f;
    int r0g = n0 + rowb + g, r1g = r0g + 8;

    issue_kv(0);

    for (int it = 0; it < 16; it++) {
        int buf = it & 1, mt = it << 6;
        asm volatile("cp.async.wait_group 0;" ::: "memory");
        __syncthreads();
        if (it + 1 < 16) issue_kv(it + 1);

        float sacc[8][4] = {};
        #pragma unroll
        for (int ks = 0; ks < 8; ks++) {
            int kk = ks * 8;
            uint32_t a[4];
            a[0] = Qs[rowb + g][kk + q];
            a[1] = Qs[rowb + g + 8][kk + q];
            a[2] = Qs[rowb + g][kk + q + 4];
            a[3] = Qs[rowb + g + 8][kk + q + 4];
            #pragma unroll
            for (int nf = 0; nf < 8; nf++) {
                uint32_t bb[2];
                bb[0] = Ks[buf][kk + q][nf * 8 + g];
                bb[1] = Ks[buf][kk + q + 4][nf * 8 + g];
                mma8(sacc[nf], a, bb);
            }
        }

        const float* mr0 = Mb + (size_t)r0g * NN + mt;
        const float* mr1 = Mb + (size_t)r1g * NN + mt;
        float v0[16], v1[16];
        float rm0 = -1e30f, rm1 = -1e30f;
        #pragma unroll
        for (int nf = 0; nf < 8; nf++) {
            int c = nf * 8 + 2 * q;
            float2 k0v = *(const float2*)&mr0[c];
            float2 k1v = *(const float2*)&mr1[c];
            v0[2 * nf]     = sacc[nf][0] * 0.125f * k0v.x;
            v0[2 * nf + 1] = sacc[nf][1] * 0.125f * k0v.y;
            v1[2 * nf]     = sacc[nf][2] * 0.125f * k1v.x;
            v1[2 * nf + 1] = sacc[nf][3] * 0.125f * k1v.y;
            rm0 = fmaxf(rm0, fmaxf(v0[2 * nf], v0[2 * nf + 1]));
            rm1 = fmaxf(rm1, fmaxf(v1[2 * nf], v1[2 * nf + 1]));
        }
        rm0 = fmaxf(rm0, __shfl_xor_sync(0xffffffffu, rm0, 1));
        rm0 = fmaxf(rm0, __shfl_xor_sync(0xffffffffu, rm0, 2));
        rm1 = fmaxf(rm1, __shfl_xor_sync(0xffffffffu, rm1, 1));
        rm1 = fmaxf(rm1, __shfl_xor_sync(0xffffffffu, rm1, 2));
        float nm0 = fmaxf(m0r, rm0), nm1 = fmaxf(m1r, rm1);
        float rs0 = 0.f, rs1 = 0.f;
        #pragma unroll
        for (int i = 0; i < 16; i++) {
            v0[i] = __expf(v0[i] - nm0); rs0 += v0[i];
            v1[i] = __expf(v1[i] - nm1); rs1 += v1[i];
        }
        rs0 += __shfl_xor_sync(0xffffffffu, rs0, 1);
        rs0 += __shfl_xor_sync(0xffffffffu, rs0, 2);
        rs1 += __shfl_xor_sync(0xffffffffu, rs1, 1);
        rs1 += __shfl_xor_sync(0xffffffffu, rs1, 2);
        float f0 = __expf(m0r - nm0), f1 = __expf(m1r - nm1);
        m0r = nm0; m1r = nm1;
        l0 = l0 * f0 + rs0;
        l1 = l1 * f1 + rs1;

        {
            float fA = __shfl_sync(0xffffffffu, f0, 8 * q);
            float fB = __shfl_sync(0xffffffffu, f0, 8 * q + 4);
            float fC = __shfl_sync(0xffffffffu, f1, 8 * q);
            float fD = __shfl_sync(0xffffffffu, f1, 8 * q + 4);
            #pragma unroll
            for (int df = 0; df < 4; df++) {
                oacc[df][0][0] *= fA; oacc[df][0][1] *= fB;
                oacc[df][0][2] *= fA; oacc[df][0][3] *= fB;
                oacc[df][1][0] *= fC; oacc[df][1][1] *= fD;
                oacc[df][1][2] *= fC; oacc[df][1][3] *= fD;
            }
        }

        #pragma unroll
        for (int nf = 0; nf < 8; nf++) {
            Ps[nf * 8 + 2 * q][rowb + g]         = __float_as_uint(v0[2 * nf]);
            Ps[nf * 8 + 2 * q + 1][rowb + g]     = __float_as_uint(v0[2 * nf + 1]);
            Ps[nf * 8 + 2 * q][rowb + g + 8]     = __float_as_uint(v1[2 * nf]);
            Ps[nf * 8 + 2 * q + 1][rowb + g + 8] = __float_as_uint(v1[2 * nf + 1]);
        }
        __syncwarp();

        #pragma unroll
        for (int ks = 0; ks < 8; ks++) {
            int kk = ks * 8;
            uint32_t bb0[2], bb1[2];
            bb0[0] = Ps[kk + q][rowb + g];
            bb0[1] = Ps[kk + q + 4][rowb + g];
            bb1[0] = Ps[kk + q][rowb + 8 + g];
            bb1[1] = Ps[kk + q + 4][rowb + 8 + g];
            #pragma unroll
            for (int df = 0; df < 4; df++) {
                uint32_t a[4];
                a[0] = Vs[buf][df * 16 + g][kk + q];
                a[1] = Vs[buf][df * 16 + 8 + g][kk + q];
                a[2] = Vs[buf][df * 16 + g][kk + q + 4];
                a[3] = Vs[buf][df * 16 + 8 + g][kk + q + 4];
                mma8(oacc[df][0], a, bb0);
                mma8(oacc[df][1], a, bb1);
            }
        }
        __syncwarp();
    }

    float invA = 1.0f / __shfl_sync(0xffffffffu, l0, 8 * q);
    float invB = 1.0f / __shfl_sync(0xffffffffu, l0, 8 * q + 4);
    float invC = 1.0f / __shfl_sync(0xffffffffu, l1, 8 * q);
    float invD = 1.0f / __shfl_sync(0xffffffffu, l1, 8 * q + 4);
    __syncthreads();
    #pragma unroll
    for (int df = 0; df < 4; df++) {
        int d0 = df * 16 + g, d1 = d0 + 8;
        float2 p;
        p.x = oacc[df][0][0] * invA; p.y = oacc[df][0][1] * invB;
        *(float2*)&Osf[d0][rowb + 2 * q] = p;
        p.x = oacc[df][0][2] * invA; p.y = oacc[df][0][3] * invB;
        *(float2*)&Osf[d1][rowb + 2 * q] = p;
        p.x = oacc[df][1][0] * invC; p.y = oacc[df][1][1] * invD;
        *(float2*)&Osf[d0][rowb + 8 + 2 * q] = p;
        p.x = oacc[df][1][2] * invC; p.y = oacc[df][1][3] * invD;
        *(float2*)&Osf[d1][rowb + 8 + 2 * q] = p;
    }
    __syncthreads();
    {
        int d = t >> 1, nc = (t & 1) * 32;
        float* op = &Xatt[(size_t)b * Dd * NN + (size_t)(d * 4 + h) * NN + n0 + nc];
        #pragma unroll
        for (int u = 0; u < 8; u++)
            *(float4*)(op + u * 4) = *(const float4*)&Osf[d][nc + u * 4];
    }
}

// ---------------------------------------------------------------------------
extern "C" void kernel_launch(void* const* d_in, const int* in_sizes, int n_in,
                              void* d_out, int out_size)
{
    const float* desc0 = (const float*)d_in[0];
    const float* desc1 = (const float*)d_in[1];
    const float* M0    = (const float*)d_in[2];
    const float* M1    = (const float*)d_in[3];
    const float* Wq = (const float*)d_in[4];
    const float* bq = (const float*)d_in[5];
    const float* Wk = (const float*)d_in[6];
    const float* bk = (const float*)d_in[7];
    const float* Wv = (const float*)d_in[8];
    const float* bv = (const float*)d_in[9];
    const float* Wm = (const float*)d_in[10];
    const float* bm = (const float*)d_in[11];
    const float* W1 = (const float*)d_in[12];
    const float* b1 = (const float*)d_in[13];
    const float* g1 = (const float*)d_in[14];
    const float* be1 = (const float*)d_in[15];
    const float* W2 = (const float*)d_in[16];
    const float* b2 = (const float*)d_in[17];

    float* Dsc = (float*)d_out;   // [4, 256, 1024] — doubles as the output

    float *Q, *K, *V, *Xatt, *Y1, *W1c, *b1c;
    cudaGetSymbolAddress((void**)&Q,    g_Q);
    cudaGetSymbolAddress((void**)&K,    g_K);
    cudaGetSymbolAddress((void**)&V,    g_V);
    cudaGetSymbolAddress((void**)&Xatt, g_Xatt);
    cudaGetSymbolAddress((void**)&Y1,   g_Y1);
    cudaGetSymbolAddress((void**)&W1c,  g_W1c);
    cudaGetSymbolAddress((void**)&b1c,  g_b1c);

    static const int ATTN_SMEM = (64 * 68 + 2 * 64 * 72 + 2 * 64 * 68 + 64 * 72) * 4; // 107520
    static const int CPA_SMEM  = (3 * 64 * 36 + 3 * 32 * 136) * 4;                    // 79872
    cudaFuncSetAttribute(attn_mma,  cudaFuncAttributeMaxDynamicSharedMemorySize, ATTN_SMEM);
    cudaFuncSetAttribute(qkv_mma,   cudaFuncAttributeMaxDynamicSharedMemorySize, CPA_SMEM);
    cudaFuncSetAttribute(conv1_mma, cudaFuncAttributeMaxDynamicSharedMemorySize, CPA_SMEM);

    size_t descBytes = (size_t)2 * Dd * NN * sizeof(float);
    cudaMemcpyAsync(Dsc,               desc0, descBytes, cudaMemcpyDeviceToDevice, 0);
    cudaMemcpyAsync(Dsc + 2 * Dd * NN, desc1, descBytes, cudaMemcpyDeviceToDevice, 0);

    // One-shot composite-weight precompute (merge GEMM folded into conv1)
    copy_w1a<<<768, 256>>>(W1);
    compose_w1<<<dim3(4, 8, LL), 256>>>(W1, Wm);
    compose_b1<<<(LL * D2) / 256, 256>>>(W1, bm, b1);

    static const int crossFlag[LL] = {0, 1, 0, 1, 0, 1};

    for (int i = 0; i < LL; i++) {
        int xm = crossFlag[i] ? 2 : 0;
        const float* Wqi = Wq + (size_t)i * Dd * Dd;
        const float* bqi = bq + (size_t)i * Dd;
        const float* Wki = Wk + (size_t)i * Dd * Dd;
        const float* bki = bk + (size_t)i * Dd;
        const float* Wvi = Wv + (size_t)i * Dd * Dd;
        const float* bvi = bv + (size_t)i * Dd;
        const float* g1i = g1 + (size_t)i * D2;
        const float* be1i = be1 + (size_t)i * D2;
        const float* W2i = W2 + (size_t)i * Dd * D2;
        const float* b2i = b2 + (size_t)i * Dd;

        // Fused Q/K/V projections; block 0 zeroes BN accumulators for conv1
        qkv_mma<<<dim3(8, 12, 4), 256, CPA_SMEM>>>(Wqi, bqi, Wki, bki, Wvi, bvi,
                                                   Dsc, xm, Q, K, V);

        attn_mma<<<dim3(16, 16), 128, ATTN_SMEM>>>(Q, K, V, M0, M1, Xatt);

        // conv1 with composite weights on [Dsc ; Xatt]; BN stats fused in epilogue
        conv1_mma<<<dim3(8, 8, 4), 256, CPA_SMEM>>>(W1c + (size_t)i * D2 * D2,
                                                    b1c + (size_t)i * D2,
                                                    Dsc, Xatt, Y1);

        // conv2: per-block BN finalize (from accumulators) + BN+ReLU + residual
        conv_bnrelu<<<dim3(8, 4, 4), 256>>>(W2i, b2i, g1i, be1i, Y1, Dsc);
    }
}